// round 8
// baseline (speedup 1.0000x reference)
#include <cuda_runtime.h>
#include <cuda_bf16.h>
#include <cstdint>

// ---------------------------------------------------------------------------
// MultiScaleMambaEncoder — all GEMMs on mma.sync bf16 hi/lo x3 + chunked scan
// ---------------------------------------------------------------------------

#define BB 4
#define CC 512
#define DIN 1024
#define RTOK 8192

// fp32 scratch
__device__ float g_xz[RTOK * 2 * DIN];
__device__ float g_x[RTOK * DIN];          // conv output, then ylin (pass A)
__device__ float g_xdbl[RTOK * 64];
__device__ float g_P[16 * 128 * 1024];     // per-chunk dA product
__device__ float g_hch[16 * 128 * 1024];   // per-chunk local h, then h_in
__device__ float g_delta[RTOK * DIN];
__device__ float g_o[RTOK * CC];
// bf16 hi/lo scratch
__device__ __nv_bfloat16 g_ah[RTOK * DIN];
__device__ __nv_bfloat16 g_al[RTOK * DIN];
__device__ __nv_bfloat16 g_dth[RTOK * 32];
__device__ __nv_bfloat16 g_dtl[RTOK * 32];
__device__ __nv_bfloat16 g_wih[6 * 2048 * 512];
__device__ __nv_bfloat16 g_wil[6 * 2048 * 512];
__device__ __nv_bfloat16 g_woh[6 * 512 * 1024];
__device__ __nv_bfloat16 g_wol[6 * 512 * 1024];
__device__ __nv_bfloat16 g_xwh[6 * 64 * 1024];
__device__ __nv_bfloat16 g_xwl[6 * 64 * 1024];
__device__ __nv_bfloat16 g_dwh[6 * 1024 * 32];
__device__ __nv_bfloat16 g_dwl[6 * 1024 * 32];

__device__ __forceinline__ int wsel4(int ml, int w0, int w1, int w2, int w3) {
    return ml == 0 ? w0 : ml == 1 ? w1 : ml == 2 ? w2 : w3;
}

__device__ __forceinline__ uint32_t smem_u32(const void* p) {
    uint32_t a;
    asm("{ .reg .u64 t; cvta.to.shared.u64 t, %1; cvt.u32.u64 %0, t; }" : "=r"(a) : "l"(p));
    return a;
}
#define CP16(dst, src)  asm volatile("cp.async.cg.shared.global [%0], [%1], 16;" :: "r"(dst), "l"(src))
#define CP_COMMIT()     asm volatile("cp.async.commit_group;" ::: "memory")
#define CP_WAIT0()      asm volatile("cp.async.wait_group 0;" ::: "memory")

#define LDM4(r0, r1, r2, r3, a) \
    asm volatile("ldmatrix.sync.aligned.m8n8.x4.shared.b16 {%0,%1,%2,%3}, [%4];" \
                 : "=r"(r0), "=r"(r1), "=r"(r2), "=r"(r3) : "r"(a))
#define LDM2(r0, r1, a) \
    asm volatile("ldmatrix.sync.aligned.m8n8.x2.shared.b16 {%0,%1}, [%2];" \
                 : "=r"(r0), "=r"(r1) : "r"(a))
#define MMA16816(d, a, b) \
    asm volatile("mma.sync.aligned.m16n8k16.row.col.f32.bf16.bf16.f32 " \
                 "{%0,%1,%2,%3},{%4,%5,%6,%7},{%8,%9},{%0,%1,%2,%3};" \
                 : "+f"((d)[0]), "+f"((d)[1]), "+f"((d)[2]), "+f"((d)[3]) \
                 : "r"((a)[0]), "r"((a)[1]), "r"((a)[2]), "r"((a)[3]), \
                   "r"((b)[0]), "r"((b)[1]))

__device__ __forceinline__ void hilo(float v, __nv_bfloat16& h, __nv_bfloat16& l) {
    h = __float2bfloat16(v);
    l = __float2bfloat16(v - __bfloat162float(h));
}
__device__ __forceinline__ float softplusf(float x) {
    return (x > 15.f) ? x : __logf(1.f + __expf(x));
}
// powers: p[s] = e1^(s+1), depth-4 ladder
__device__ __forceinline__ void powers16(float e1, float* p) {
    float e2 = e1 * e1, e4 = e2 * e2, e8 = e4 * e4;
    p[0] = e1;        p[1] = e2;        p[2] = e2 * e1;   p[3] = e4;
    p[4] = e4 * e1;   p[5] = e4 * e2;   p[6] = e4 * p[2]; p[7] = e8;
    p[8] = e8 * e1;   p[9] = e8 * e2;   p[10] = e8 * p[2]; p[11] = e8 * e4;
    p[12] = e8 * p[4]; p[13] = e8 * p[5]; p[14] = e8 * p[6]; p[15] = e8 * e8;
}

// ---------------------------------------------------------------------------
__global__ void k_cvt(const float* __restrict__ src, __nv_bfloat16* __restrict__ hi,
                      __nv_bfloat16* __restrict__ lo, int n) {
    int i = blockIdx.x * blockDim.x + threadIdx.x;
    if (i >= n) return;
    float v = src[i];
    hilo(v, hi[i], lo[i]);
}

// layer-0 inputs (cat fwd+rev), emitted directly as bf16 hi/lo
__global__ void k_build_cat(const float* __restrict__ s0, const float* __restrict__ s1,
                            const float* __restrict__ s2, const float* __restrict__ s3) {
    int idx = blockIdx.x * blockDim.x + threadIdx.x;
    if (idx >= RTOK * CC) return;
    int c = idx & (CC - 1);
    int r = idx >> 9;
    int t = r & 511;
    int b = (r >> 9) & 3;
    int slot = r >> 11;
    const float* s = slot == 0 ? s0 : slot == 1 ? s1 : slot == 2 ? s2 : s3;
    int tt = t < 256 ? t : 511 - t;
    float v = s[(b * 256 + tt) * CC + c];
    hilo(v, g_ah[idx], g_al[idx]);
}

// ---------------------------------------------------------------------------
// mma.sync GEMM: C = A * W^T (bf16 hi/lo x3), 128x128 tile, BK=32,
// 2-stage cp.async double buffer, 2 CTAs/SM. Optional fused bias+softplus.
// ---------------------------------------------------------------------------
#define MM_STAGE 40960
#define MM_TILE  10240

__global__ __launch_bounds__(256, 2) void k_mma(
    const __nv_bfloat16* __restrict__ Ah, const __nv_bfloat16* __restrict__ Al,
    const __nv_bfloat16* __restrict__ WhB, const __nv_bfloat16* __restrict__ WlB,
    float* __restrict__ C, int K, int ldc,
    int rpg, int wstride, int w0, int w1, int w2, int w3,
    const float* __restrict__ bias) {
    extern __shared__ __align__(128) uint8_t smraw[];
    const uint32_t smb = smem_u32(smraw);
    const int tid = threadIdx.x;
    const int wid = tid >> 5;
    const int lane = tid & 31;
    const int wm = wid >> 2;
    const int wn = wid & 3;
    const int row0 = blockIdx.y * 128;
    const int col0 = blockIdx.x * 128;
    const int wsel = wsel4(row0 / rpg, w0, w1, w2, w3);
    const __nv_bfloat16* Wh = WhB + (size_t)wsel * wstride;
    const __nv_bfloat16* Wl = WlB + (size_t)wsel * wstride;
    const int nc = K >> 5;

    float acc[4][4][4];
#pragma unroll
    for (int i = 0; i < 4; i++)
#pragma unroll
        for (int j = 0; j < 4; j++)
#pragma unroll
            for (int q = 0; q < 4; q++) acc[i][j][q] = 0.f;

    auto load_stage = [&](int kc, int st) {
        const int k0 = kc << 5;
        const uint32_t sb = smb + st * MM_STAGE;
#pragma unroll
        for (int p = 0; p < 8; p++) {
            int u = tid + (p << 8);
            int tile = u >> 9;
            int v = u & 511;
            int r = v >> 2, seg = v & 3;
            const __nv_bfloat16* src;
            if (tile == 0)      src = Ah + (size_t)(row0 + r) * K;
            else if (tile == 1) src = Al + (size_t)(row0 + r) * K;
            else if (tile == 2) src = Wh + (size_t)(col0 + r) * K;
            else                src = Wl + (size_t)(col0 + r) * K;
            CP16(sb + tile * MM_TILE + r * 80 + seg * 16, src + k0 + seg * 8);
        }
        CP_COMMIT();
    };

    load_stage(0, 0);
    CP_WAIT0();
    __syncthreads();

    const uint32_t aRowByte = (uint32_t)(wm * 64 + (lane & 15)) * 80 + ((lane >> 4) << 4);
    const uint32_t bRowByte = (uint32_t)(wn * 32 + (lane & 7)) * 80 + (((lane >> 3) & 1) << 4);

    for (int c = 0; c < nc; c++) {
        const int st = c & 1;
        if (c + 1 < nc) load_stage(c + 1, st ^ 1);
        const uint32_t sb = smb + st * MM_STAGE;
#pragma unroll
        for (int ks = 0; ks < 2; ks++) {
            uint32_t ah[4][4], al[4][4], bh[4][2], bl[4][2];
            const uint32_t kb = ks * 32;
#pragma unroll
            for (int mi = 0; mi < 4; mi++) {
                uint32_t ra = sb + aRowByte + (uint32_t)mi * 16 * 80 + kb;
                LDM4(ah[mi][0], ah[mi][1], ah[mi][2], ah[mi][3], ra);
                LDM4(al[mi][0], al[mi][1], al[mi][2], al[mi][3], ra + MM_TILE);
            }
#pragma unroll
            for (int ni = 0; ni < 4; ni++) {
                uint32_t rb = sb + 2 * MM_TILE + bRowByte + (uint32_t)ni * 8 * 80 + kb;
                LDM2(bh[ni][0], bh[ni][1], rb);
                LDM2(bl[ni][0], bl[ni][1], rb + MM_TILE);
            }
#pragma unroll
            for (int mi = 0; mi < 4; mi++)
#pragma unroll
                for (int ni = 0; ni < 4; ni++) {
                    MMA16816(acc[mi][ni], ah[mi], bh[ni]);
                    MMA16816(acc[mi][ni], ah[mi], bl[ni]);
                    MMA16816(acc[mi][ni], al[mi], bh[ni]);
                }
        }
        if (c + 1 < nc) CP_WAIT0();
        __syncthreads();
    }

    const int gr = lane >> 2;
    const int gc = (lane & 3) * 2;
    const float* bp = bias ? bias + wsel * 1024 : nullptr;
#pragma unroll
    for (int mi = 0; mi < 4; mi++)
#pragma unroll
        for (int ni = 0; ni < 4; ni++) {
            int row = row0 + wm * 64 + mi * 16 + gr;
            int col = col0 + wn * 32 + ni * 8 + gc;
            float4 v = make_float4(acc[mi][ni][0], acc[mi][ni][1],
                                   acc[mi][ni][2], acc[mi][ni][3]);
            if (bp) {
                float b0 = bp[col], b1 = bp[col + 1];
                v.x = softplusf(v.x + b0); v.y = softplusf(v.y + b1);
                v.z = softplusf(v.z + b0); v.w = softplusf(v.w + b1);
            }
            float* p0 = C + (size_t)row * ldc + col;
            float* p1 = C + (size_t)(row + 8) * ldc + col;
            *(float2*)p0 = make_float2(v.x, v.y);
            *(float2*)p1 = make_float2(v.z, v.w);
        }
}

// ---------------------------------------------------------------------------
// x_proj GEMM: g_xdbl[RTOK,64] = x * xw^T, CTA 128x64, warp tile 32x32, BK=32.
// Also emits dt columns (col<32) as bf16 hi/lo for the dt GEMM.
// ---------------------------------------------------------------------------
#define MX_STAGE 30720
#define MX_ATILE 10240
#define MX_WTILE 5120

__global__ __launch_bounds__(256) void k_mmax(
    const __nv_bfloat16* __restrict__ Ah, const __nv_bfloat16* __restrict__ Al,
    const __nv_bfloat16* __restrict__ WhB, const __nv_bfloat16* __restrict__ WlB,
    int rpg, int w0, int w1, int w2, int w3) {
    extern __shared__ __align__(128) uint8_t smraw[];
    const uint32_t smb = smem_u32(smraw);
    const int tid = threadIdx.x;
    const int wid = tid >> 5;
    const int lane = tid & 31;
    const int wm = wid >> 1;            // 0..3 -> 32-row groups
    const int wn = wid & 1;             // 0..1 -> 32-col groups
    const int row0 = blockIdx.y * 128;
    const int wsel = wsel4(row0 / rpg, w0, w1, w2, w3);
    const __nv_bfloat16* Wh = WhB + (size_t)wsel * (64 * 1024);
    const __nv_bfloat16* Wl = WlB + (size_t)wsel * (64 * 1024);
    const int K = 1024, nc = 32;

    float acc[2][4][4];
#pragma unroll
    for (int i = 0; i < 2; i++)
#pragma unroll
        for (int j = 0; j < 4; j++)
#pragma unroll
            for (int q = 0; q < 4; q++) acc[i][j][q] = 0.f;

    auto load_stage = [&](int kc, int st) {
        const int k0 = kc << 5;
        const uint32_t sb = smb + st * MX_STAGE;
#pragma unroll
        for (int p = 0; p < 6; p++) {
            int u = tid + (p << 8);
            if (u < 1024) {             // A tiles: 128 rows x 4 segs x 2
                int tile = u >> 9;
                int v = u & 511;
                int r = v >> 2, seg = v & 3;
                const __nv_bfloat16* src = (tile ? Al : Ah) + (size_t)(row0 + r) * K;
                CP16(sb + tile * MX_ATILE + r * 80 + seg * 16, src + k0 + seg * 8);
            } else {                    // W tiles: 64 rows x 4 segs x 2
                int u2 = u - 1024;
                int tile = u2 >> 8;
                int v = u2 & 255;
                int r = v >> 2, seg = v & 3;
                const __nv_bfloat16* src = (tile ? Wl : Wh) + (size_t)r * K;
                CP16(sb + 2 * MX_ATILE + tile * MX_WTILE + r * 80 + seg * 16,
                     src + k0 + seg * 8);
            }
        }
        CP_COMMIT();
    };

    load_stage(0, 0);
    CP_WAIT0();
    __syncthreads();

    const uint32_t aRowByte = (uint32_t)(wm * 32 + (lane & 15)) * 80 + ((lane >> 4) << 4);
    const uint32_t bRowByte = (uint32_t)(wn * 32 + (lane & 7)) * 80 + (((lane >> 3) & 1) << 4);

    for (int c = 0; c < nc; c++) {
        const int st = c & 1;
        if (c + 1 < nc) load_stage(c + 1, st ^ 1);
        const uint32_t sb = smb + st * MX_STAGE;
#pragma unroll
        for (int ks = 0; ks < 2; ks++) {
            uint32_t ah[2][4], al[2][4], bh[4][2], bl[4][2];
            const uint32_t kb = ks * 32;
#pragma unroll
            for (int mi = 0; mi < 2; mi++) {
                uint32_t ra = sb + aRowByte + (uint32_t)mi * 16 * 80 + kb;
                LDM4(ah[mi][0], ah[mi][1], ah[mi][2], ah[mi][3], ra);
                LDM4(al[mi][0], al[mi][1], al[mi][2], al[mi][3], ra + MX_ATILE);
            }
#pragma unroll
            for (int ni = 0; ni < 4; ni++) {
                uint32_t rb = sb + 2 * MX_ATILE + bRowByte + (uint32_t)ni * 8 * 80 + kb;
                LDM2(bh[ni][0], bh[ni][1], rb);
                LDM2(bl[ni][0], bl[ni][1], rb + MX_WTILE);
            }
#pragma unroll
            for (int mi = 0; mi < 2; mi++)
#pragma unroll
                for (int ni = 0; ni < 4; ni++) {
                    MMA16816(acc[mi][ni], ah[mi], bh[ni]);
                    MMA16816(acc[mi][ni], ah[mi], bl[ni]);
                    MMA16816(acc[mi][ni], al[mi], bh[ni]);
                }
        }
        if (c + 1 < nc) CP_WAIT0();
        __syncthreads();
    }

    const int gr = lane >> 2;
    const int gc = (lane & 3) * 2;
#pragma unroll
    for (int mi = 0; mi < 2; mi++)
#pragma unroll
        for (int ni = 0; ni < 4; ni++) {
            int row = row0 + wm * 32 + mi * 16 + gr;
            int col = wn * 32 + ni * 8 + gc;
            float* p0 = g_xdbl + (size_t)row * 64 + col;
            float* p1 = g_xdbl + (size_t)(row + 8) * 64 + col;
            *(float2*)p0 = make_float2(acc[mi][ni][0], acc[mi][ni][1]);
            *(float2*)p1 = make_float2(acc[mi][ni][2], acc[mi][ni][3]);
            if (wn == 0) {  // dt columns -> bf16 hi/lo for the dt GEMM
                hilo(acc[mi][ni][0], g_dth[(size_t)row * 32 + col],
                     g_dtl[(size_t)row * 32 + col]);
                hilo(acc[mi][ni][1], g_dth[(size_t)row * 32 + col + 1],
                     g_dtl[(size_t)row * 32 + col + 1]);
                hilo(acc[mi][ni][2], g_dth[(size_t)(row + 8) * 32 + col],
                     g_dtl[(size_t)(row + 8) * 32 + col]);
                hilo(acc[mi][ni][3], g_dth[(size_t)(row + 8) * 32 + col + 1],
                     g_dtl[(size_t)(row + 8) * 32 + col + 1]);
            }
        }
}

// ---------------------------------------------------------------------------
// causal depthwise conv (4 taps) + bias + SiLU; emits fp32 + bf16 hi/lo
// ---------------------------------------------------------------------------
__global__ void k_conv(const float* __restrict__ cw, const float* __restrict__ cb,
                       int T, int rpg, int w0, int w1, int w2, int w3) {
    int idx = blockIdx.x * blockDim.x + threadIdx.x;
    if (idx >= RTOK * DIN) return;
    int d = idx & (DIN - 1);
    int r = idx >> 10;
    int t = r & (T - 1);
    int m = wsel4(r / rpg, w0, w1, w2, w3);
    const float* cwp = cw + ((size_t)m * DIN + d) * 4;
    float acc = cb[m * DIN + d];
    int base = r * (2 * DIN) + d;
#pragma unroll
    for (int k = 0; k < 4; k++) {
        int tt = t - 3 + k;
        if (tt >= 0) acc = fmaf(cwp[k], g_xz[base + (k - 3) * (2 * DIN)], acc);
    }
    float e = __expf(-acc);
    float v = __fdividef(acc, 1.f + e);
    g_x[idx] = v;
    hilo(v, g_ah[idx], g_al[idx]);
}

// ---------------------------------------------------------------------------
// Chunked selective scan (passes A, B, C).
// ---------------------------------------------------------------------------
template <bool CHAIN>
__device__ __forceinline__ void scanA_body(int rbase, int d, int g,
                                           const float Av[16], float Dv) {
    float h[16];
#pragma unroll
    for (int s = 0; s < 16; s++) h[s] = 0.f;
    float dsum = 0.f;
#pragma unroll 2
    for (int t = 0; t < 64; t++) {
        int r = rbase + t;
        float delta = g_delta[(size_t)r * DIN + d];
        float xv = g_x[(size_t)r * DIN + d];
        const float4* bc = (const float4*)(g_xdbl + (size_t)r * 64 + 32);
        float4 Bq[4], Cq[4];
#pragma unroll
        for (int q = 0; q < 4; q++) { Bq[q] = bc[q]; Cq[q] = bc[q + 4]; }
        const float* Bv = (const float*)Bq;
        const float* Cv = (const float*)Cq;
        dsum += delta;
        float p[16];
        if (CHAIN) powers16(__expf(delta * Av[0]), p);
        else {
#pragma unroll
            for (int s = 0; s < 16; s++) p[s] = __expf(delta * Av[s]);
        }
        float dx = delta * xv;
        float y0 = 0.f, y1 = 0.f, y2 = 0.f, y3 = 0.f;
#pragma unroll
        for (int s = 0; s < 16; s++) {
            h[s] = fmaf(h[s], p[s], dx * Bv[s]);
            float hv = h[s] * Cv[s];
            if ((s & 3) == 0) y0 += hv;
            else if ((s & 3) == 1) y1 += hv;
            else if ((s & 3) == 2) y2 += hv;
            else y3 += hv;
        }
        g_x[(size_t)r * DIN + d] = fmaf(Dv, xv, (y0 + y1) + (y2 + y3));
    }
    float P[16];
    if (CHAIN) powers16(__expf(dsum * Av[0]), P);
    else {
#pragma unroll
        for (int s = 0; s < 16; s++) P[s] = __expf(dsum * Av[s]);
    }
#pragma unroll
    for (int s = 0; s < 16; s++) {
        size_t o = ((size_t)(s * 128 + g) << 10) + d;
        g_hch[o] = h[s];
        g_P[o] = P[s];
    }
}

__global__ __launch_bounds__(128) void k_scanA(const float* __restrict__ Alog,
                                               const float* __restrict__ Dp,
                                               int lgNCH, int w0, int w1, int w2, int w3) {
    int blk = blockIdx.x;
    int dg = blk & 7;
    int g = blk >> 3;
    int seq = g >> lgNCH;
    int d = (dg << 7) | threadIdx.x;
    int m = wsel4(seq >> 2, w0, w1, w2, w3);
    float Av[16];
    const float* ap = Alog + ((size_t)m * DIN + d) * 16;
#pragma unroll
    for (int s = 0; s < 16; s++) Av[s] = -__expf(ap[s]);
    bool chain = true;
#pragma unroll
    for (int s = 1; s < 16; s++)
        chain = chain &&
                (fabsf(Av[s] - (float)(s + 1) * Av[0]) <=
                 1e-3f * (float)(s + 1) * fabsf(Av[0]) + 1e-7f);
    float Dv = Dp[m * DIN + d];
    int rbase = g << 6;
    if (chain) scanA_body<true>(rbase, d, g, Av, Dv);
    else       scanA_body<false>(rbase, d, g, Av, Dv);
}

__global__ void k_scanB(int lgNCH, int nseq) {
    int idx = blockIdx.x * blockDim.x + threadIdx.x;
    if (idx >= nseq * DIN) return;
    int seq = idx >> 10;
    int d = idx & 1023;
    int NCH = 1 << lgNCH;
    float hin[16];
#pragma unroll
    for (int s = 0; s < 16; s++) hin[s] = 0.f;
    for (int j = 0; j < NCH; j++) {
        int g = (seq << lgNCH) + j;
#pragma unroll
        for (int s = 0; s < 16; s++) {
            size_t o = ((size_t)(s * 128 + g) << 10) + d;
            float hl = g_hch[o];
            float Pp = g_P[o];
            g_hch[o] = hin[s];
            hin[s] = fmaf(Pp, hin[s], hl);
        }
    }
}

template <bool CHAIN>
__device__ __forceinline__ void scanC_body(int rbase, int d, int g,
                                           const float Av[16]) {
    float q[16];
#pragma unroll
    for (int s = 0; s < 16; s++)
        q[s] = g_hch[((size_t)(s * 128 + g) << 10) + d];
#pragma unroll 2
    for (int t = 0; t < 64; t++) {
        int r = rbase + t;
        float delta = g_delta[(size_t)r * DIN + d];
        float zv = g_xz[(size_t)r * 2048 + 1024 + d];
        float ylin = g_x[(size_t)r * DIN + d];
        const float4* cp = (const float4*)(g_xdbl + (size_t)r * 64 + 48);
        float4 Cq[4];
#pragma unroll
        for (int u = 0; u < 4; u++) Cq[u] = cp[u];
        const float* Cv = (const float*)Cq;
        float p[16];
        if (CHAIN) powers16(__expf(delta * Av[0]), p);
        else {
#pragma unroll
            for (int s = 0; s < 16; s++) p[s] = __expf(delta * Av[s]);
        }
        float c0 = 0.f, c1 = 0.f, c2 = 0.f, c3 = 0.f;
#pragma unroll
        for (int s = 0; s < 16; s++) {
            q[s] *= p[s];
            float hv = q[s] * Cv[s];
            if ((s & 3) == 0) c0 += hv;
            else if ((s & 3) == 1) c1 += hv;
            else if ((s & 3) == 2) c2 += hv;
            else c3 += hv;
        }
        float y = ylin + (c0 + c1) + (c2 + c3);
        float sg = __fdividef(zv, 1.f + __expf(-zv));
        float yv = y * sg;
        hilo(yv, g_ah[(size_t)r * DIN + d], g_al[(size_t)r * DIN + d]);
    }
}

__global__ __launch_bounds__(128) void k_scanC(const float* __restrict__ Alog,
                                               int lgNCH, int w0, int w1, int w2, int w3) {
    int blk = blockIdx.x;
    int dg = blk & 7;
    int g = blk >> 3;
    int seq = g >> lgNCH;
    int j = g & ((1 << lgNCH) - 1);
    int d = (dg << 7) | threadIdx.x;
    int rbase = g << 6;
    if (j == 0) {
#pragma unroll 2
        for (int t = 0; t < 64; t++) {
            int r = rbase + t;
            float zv = g_xz[(size_t)r * 2048 + 1024 + d];
            float ylin = g_x[(size_t)r * DIN + d];
            float sg = __fdividef(zv, 1.f + __expf(-zv));
            float yv = ylin * sg;
            hilo(yv, g_ah[(size_t)r * DIN + d], g_al[(size_t)r * DIN + d]);
        }
        return;
    }
    int m = wsel4(seq >> 2, w0, w1, w2, w3);
    float Av[16];
    const float* ap = Alog + ((size_t)m * DIN + d) * 16;
#pragma unroll
    for (int s = 0; s < 16; s++) Av[s] = -__expf(ap[s]);
    bool chain = true;
#pragma unroll
    for (int s = 1; s < 16; s++)
        chain = chain &&
                (fabsf(Av[s] - (float)(s + 1) * Av[0]) <=
                 1e-3f * (float)(s + 1) * fabsf(Av[0]) + 1e-7f);
    if (chain) scanC_body<true>(rbase, d, g, Av);
    else       scanC_body<false>(rbase, d, g, Av);
}

// ---------------------------------------------------------------------------
__global__ __launch_bounds__(128) void k_combine(
    const float* __restrict__ s0, const float* __restrict__ s1,
    const float* __restrict__ s2, const float* __restrict__ s3,
    const float* __restrict__ lnw, const float* __restrict__ lnb) {
    int blk = blockIdx.x;
    int t = blk & 255;
    int b = (blk >> 8) & 3;
    int slot = blk >> 10;
    const float* src = slot == 0 ? s0 : slot == 1 ? s1 : slot == 2 ? s2 : s3;
    int rowA = ((slot * 4 + b) * 512 + t) * CC;
    int rowB = ((slot * 4 + b) * 512 + (511 - t)) * CC;
    int tid = threadIdx.x;
    float v[4];
#pragma unroll
    for (int j = 0; j < 4; j++) {
        int c = tid + j * 128;
        v[j] = 0.5f * (g_o[rowA + c] + g_o[rowB + c]);
    }
    __shared__ float red[8];
    int wid = tid >> 5, lane = tid & 31;
    float s = (v[0] + v[1]) + (v[2] + v[3]);
#pragma unroll
    for (int o = 16; o; o >>= 1) s += __shfl_xor_sync(~0u, s, o);
    if (lane == 0) red[wid] = s;
    __syncthreads();
    float mean = (red[0] + red[1] + red[2] + red[3]) * (1.f / 512.f);
    float q = 0.f;
#pragma unroll
    for (int j = 0; j < 4; j++) { float dd = v[j] - mean; q = fmaf(dd, dd, q); }
#pragma unroll
    for (int o = 16; o; o >>= 1) q += __shfl_xor_sync(~0u, q, o);
    if (lane == 0) red[4 + wid] = q;
    __syncthreads();
    float var = (red[4] + red[5] + red[6] + red[7]) * (1.f / 512.f);
    float rstd = rsqrtf(var + 1e-5f);
    int tau = slot * 256 + t;
#pragma unroll
    for (int j = 0; j < 4; j++) {
        int c = tid + j * 128;
        float o = (v[j] - mean) * rstd * lnw[c] + lnb[c] + src[(b * 256 + t) * CC + c];
        __nv_bfloat16 hh, ll;
        hilo(o, hh, ll);
        int idxF = ((b * 1024) + tau) * CC + c;
        int idxR = (((4 + b) * 1024) + (1023 - tau)) * CC + c;
        g_ah[idxF] = hh; g_al[idxF] = ll;
        g_ah[idxR] = hh; g_al[idxR] = ll;
    }
}

__global__ void k_final(float* __restrict__ out) {
    int idx = blockIdx.x * blockDim.x + threadIdx.x;
    if (idx >= BB * 1024 * CC) return;
    int c = idx & (CC - 1);
    int rest = idx >> 9;
    int tau = rest & 1023;
    int b = rest >> 10;
    float f = 0.5f * (g_o[((b * 1024) + tau) * CC + c] +
                      g_o[(((4 + b) * 1024) + (1023 - tau)) * CC + c]);
    int i = tau >> 8;
    int t = tau & 255;
    out[(((i * 4 + b) * 256 + t) << 9) + c] = f;
}

// ---------------------------------------------------------------------------
extern "C" void kernel_launch(void* const* d_in, const int* in_sizes, int n_in,
                              void* d_out, int out_size) {
    const float* x0hw = (const float*)d_in[0];
    const float* x1hw = (const float*)d_in[1];
    const float* x0wh = (const float*)d_in[2];
    const float* x1wh = (const float*)d_in[3];
    const float* in_w = (const float*)d_in[4];
    const float* cw   = (const float*)d_in[5];
    const float* cb   = (const float*)d_in[6];
    const float* xw   = (const float*)d_in[7];
    const float* dtw  = (const float*)d_in[8];
    const float* dtb  = (const float*)d_in[9];
    const float* alog = (const float*)d_in[10];
    const float* Dp   = (const float*)d_in[11];
    const float* ow   = (const float*)d_in[12];
    const float* lnw  = (const float*)d_in[13];
    const float* lnb  = (const float*)d_in[14];
    float* out = (float*)d_out;

    float *pxz, *px, *po, *pdelta;
    cudaGetSymbolAddress((void**)&pxz, g_xz);
    cudaGetSymbolAddress((void**)&px, g_x);
    cudaGetSymbolAddress((void**)&po, g_o);
    cudaGetSymbolAddress((void**)&pdelta, g_delta);
    __nv_bfloat16 *pah, *pal, *pwih, *pwil, *pwoh, *pwol, *pxwh, *pxwl;
    __nv_bfloat16 *pdwh, *pdwl, *pdth, *pdtl;
    cudaGetSymbolAddress((void**)&pah, g_ah);
    cudaGetSymbolAddress((void**)&pal, g_al);
    cudaGetSymbolAddress((void**)&pwih, g_wih);
    cudaGetSymbolAddress((void**)&pwil, g_wil);
    cudaGetSymbolAddress((void**)&pwoh, g_woh);
    cudaGetSymbolAddress((void**)&pwol, g_wol);
    cudaGetSymbolAddress((void**)&pxwh, g_xwh);
    cudaGetSymbolAddress((void**)&pxwl, g_xwl);
    cudaGetSymbolAddress((void**)&pdwh, g_dwh);
    cudaGetSymbolAddress((void**)&pdwl, g_dwl);
    cudaGetSymbolAddress((void**)&pdth, g_dth);
    cudaGetSymbolAddress((void**)&pdtl, g_dtl);

    static int smem_set = 0;
    if (!smem_set) {
        cudaFuncSetAttribute(k_mma, cudaFuncAttributeMaxDynamicSharedMemorySize,
                             2 * MM_STAGE);
        cudaFuncSetAttribute(k_mmax, cudaFuncAttributeMaxDynamicSharedMemorySize,
                             2 * MX_STAGE);
        smem_set = 1;
    }
    const int MMSMEM = 2 * MM_STAGE;
    const int MXSMEM = 2 * MX_STAGE;

    const int EL = RTOK * DIN;
    const int EL2 = RTOK * CC;
    const int ELF = BB * 1024 * CC;

    // weights -> bf16 hi/lo
    k_cvt<<<(6 * 2048 * 512 + 255) / 256, 256>>>(in_w, pwih, pwil, 6 * 2048 * 512);
    k_cvt<<<(6 * 512 * 1024 + 255) / 256, 256>>>(ow, pwoh, pwol, 6 * 512 * 1024);
    k_cvt<<<(6 * 64 * 1024 + 255) / 256, 256>>>(xw, pxwh, pxwl, 6 * 64 * 1024);
    k_cvt<<<(6 * 1024 * 32 + 255) / 256, 256>>>(dtw, pdwh, pdwl, 6 * 1024 * 32);

    // ---------------- layer 0 (T=512, NCH=8, nseq=16) ----------------
    {
        const int w0 = 0, w1 = 2, w2 = 1, w3 = 3, rpg = 2048, T = 512, lg = 3, nseq = 16;
        k_build_cat<<<(EL2 + 255) / 256, 256>>>(x0hw, x1hw, x0wh, x1wh);
        k_mma<<<dim3(16, 64), 256, MMSMEM>>>(
            pah, pal, pwih, pwil, pxz, 512, 2048, rpg, 2048 * 512, w0, w1, w2, w3, nullptr);
        k_conv<<<(EL + 255) / 256, 256>>>(cw, cb, T, rpg, w0, w1, w2, w3);
        k_mmax<<<dim3(1, 64), 256, MXSMEM>>>(pah, pal, pxwh, pxwl, rpg, w0, w1, w2, w3);
        k_mma<<<dim3(8, 64), 256, MMSMEM>>>(
            pdth, pdtl, pdwh, pdwl, pdelta, 32, 1024, rpg, 1024 * 32,
            w0, w1, w2, w3, dtb);
        k_scanA<<<1024, 128>>>(alog, Dp, lg, w0, w1, w2, w3);
        k_scanB<<<(nseq * DIN + 255) / 256, 256>>>(lg, nseq);
        k_scanC<<<1024, 128>>>(alog, lg, w0, w1, w2, w3);
        k_mma<<<dim3(4, 64), 256, MMSMEM>>>(
            pah, pal, pwoh, pwol, po, 1024, 512, rpg, 512 * 1024, w0, w1, w2, w3, nullptr);
        k_combine<<<4096, 128>>>(x0hw, x1hw, x0wh, x1wh, lnw, lnb);
    }

    // ---------------- layer 1 (T=1024, NCH=16, nseq=8) ----------------
    {
        const int w0 = 4, w1 = 5, w2 = 4, w3 = 5, rpg = 4096, T = 1024, lg = 4, nseq = 8;
        k_mma<<<dim3(16, 64), 256, MMSMEM>>>(
            pah, pal, pwih, pwil, pxz, 512, 2048, rpg, 2048 * 512, w0, w1, w2, w3, nullptr);
        k_conv<<<(EL + 255) / 256, 256>>>(cw, cb, T, rpg, w0, w1, w2, w3);
        k_mmax<<<dim3(1, 64), 256, MXSMEM>>>(pah, pal, pxwh, pxwl, rpg, w0, w1, w2, w3);
        k_mma<<<dim3(8, 64), 256, MMSMEM>>>(
            pdth, pdtl, pdwh, pdwl, pdelta, 32, 1024, rpg, 1024 * 32,
            w0, w1, w2, w3, dtb);
        k_scanA<<<1024, 128>>>(alog, Dp, lg, w0, w1, w2, w3);
        k_scanB<<<(nseq * DIN + 255) / 256, 256>>>(lg, nseq);
        k_scanC<<<1024, 128>>>(alog, lg, w0, w1, w2, w3);
        k_mma<<<dim3(4, 64), 256, MMSMEM>>>(
            pah, pal, pwoh, pwol, po, 1024, 512, rpg, 512 * 1024, w0, w1, w2, w3, nullptr);
        k_final<<<(ELF + 255) / 256, 256>>>(out);
    }
}

// round 9
// speedup vs baseline: 1.0662x; 1.0662x over previous
#include <cuda_runtime.h>
#include <cuda_bf16.h>
#include <cstdint>

// ---------------------------------------------------------------------------
// MultiScaleMambaEncoder — mma.sync bf16 hi/lo x3 GEMMs + chunked parallel scan
// Layer-0 in_proj computed on 4096 unique rows (cat = [s; rev(s)] shares rows).
// ---------------------------------------------------------------------------

#define BB 4
#define CC 512
#define DIN 1024
#define RTOK 8192

// fp32 scratch
__device__ float g_xz[RTOK * 2 * DIN];
__device__ float g_x[RTOK * DIN];          // conv output, then ylin (pass A)
__device__ float g_xdbl[RTOK * 64];
__device__ float g_xdblp[4 * RTOK * 64];   // split-K partials; reused as P-chunk
__device__ float g_hch[16 * 128 * 1024];   // per-chunk local h, then h_in
__device__ float g_delta[RTOK * DIN];
__device__ float g_o[RTOK * CC];
// bf16 hi/lo scratch (GEMM A operands)
__device__ __nv_bfloat16 g_ah[RTOK * DIN];
__device__ __nv_bfloat16 g_al[RTOK * DIN];
__device__ __nv_bfloat16 g_wih[6 * 2048 * 512];
__device__ __nv_bfloat16 g_wil[6 * 2048 * 512];
__device__ __nv_bfloat16 g_woh[6 * 512 * 1024];
__device__ __nv_bfloat16 g_wol[6 * 512 * 1024];

__device__ __forceinline__ int wsel4(int ml, int w0, int w1, int w2, int w3) {
    return ml == 0 ? w0 : ml == 1 ? w1 : ml == 2 ? w2 : w3;
}

#define FMA2(d, a, b) asm("fma.rn.f32x2 %0, %1, %2, %0;" : "+l"(d) : "l"(a), "l"(b))
#define DUP2(d, s)    asm("mov.b64 %0, {%1, %1};" : "=l"(d) : "f"(s))

__device__ __forceinline__ uint32_t smem_u32(const void* p) {
    uint32_t a;
    asm("{ .reg .u64 t; cvta.to.shared.u64 t, %1; cvt.u32.u64 %0, t; }" : "=r"(a) : "l"(p));
    return a;
}
#define CP16(dst, src)  asm volatile("cp.async.cg.shared.global [%0], [%1], 16;" :: "r"(dst), "l"(src))
#define CP_COMMIT()     asm volatile("cp.async.commit_group;" ::: "memory")
#define CP_WAIT0()      asm volatile("cp.async.wait_group 0;" ::: "memory")

#define LDM4(r0, r1, r2, r3, a) \
    asm volatile("ldmatrix.sync.aligned.m8n8.x4.shared.b16 {%0,%1,%2,%3}, [%4];" \
                 : "=r"(r0), "=r"(r1), "=r"(r2), "=r"(r3) : "r"(a))
#define LDM2(r0, r1, a) \
    asm volatile("ldmatrix.sync.aligned.m8n8.x2.shared.b16 {%0,%1}, [%2];" \
                 : "=r"(r0), "=r"(r1) : "r"(a))
#define MMA16816(d, a, b) \
    asm volatile("mma.sync.aligned.m16n8k16.row.col.f32.bf16.bf16.f32 " \
                 "{%0,%1,%2,%3},{%4,%5,%6,%7},{%8,%9},{%0,%1,%2,%3};" \
                 : "+f"((d)[0]), "+f"((d)[1]), "+f"((d)[2]), "+f"((d)[3]) \
                 : "r"((a)[0]), "r"((a)[1]), "r"((a)[2]), "r"((a)[3]), \
                   "r"((b)[0]), "r"((b)[1]))

__device__ __forceinline__ void hilo(float v, __nv_bfloat16& h, __nv_bfloat16& l) {
    h = __float2bfloat16(v);
    l = __float2bfloat16(v - __bfloat162float(h));
}
// powers: p[s] = e1^(s+1), depth-4 ladder
__device__ __forceinline__ void powers16(float e1, float* p) {
    float e2 = e1 * e1, e4 = e2 * e2, e8 = e4 * e4;
    p[0] = e1;        p[1] = e2;        p[2] = e2 * e1;   p[3] = e4;
    p[4] = e4 * e1;   p[5] = e4 * e2;   p[6] = e4 * p[2]; p[7] = e8;
    p[8] = e8 * e1;   p[9] = e8 * e2;   p[10] = e8 * p[2]; p[11] = e8 * e4;
    p[12] = e8 * p[4]; p[13] = e8 * p[5]; p[14] = e8 * p[6]; p[15] = e8 * e8;
}
// layer-0 xz row map: r in [0,8192) -> unique row in [0,4096)
__device__ __forceinline__ int xzrow(int r, int dup) {
    if (!dup) return r;
    int t = r & 511;
    int tt = t < 256 ? t : 511 - t;
    return ((r >> 9) << 8) + tt;
}

// ---------------------------------------------------------------------------
__global__ void k_cvt(const float* __restrict__ src, __nv_bfloat16* __restrict__ hi,
                      __nv_bfloat16* __restrict__ lo, int n) {
    int i = blockIdx.x * blockDim.x + threadIdx.x;
    if (i >= n) return;
    float v = src[i];
    hilo(v, hi[i], lo[i]);
}

// layer-0 compact inputs: 4096 unique rows = (slot, b, t<256)
__global__ void k_build4(const float* __restrict__ s0, const float* __restrict__ s1,
                         const float* __restrict__ s2, const float* __restrict__ s3) {
    int idx = blockIdx.x * blockDim.x + threadIdx.x;
    if (idx >= 4096 * CC) return;
    int c = idx & (CC - 1);
    int r = idx >> 9;                    // 0..4095
    int slot = r >> 10;
    const float* s = slot == 0 ? s0 : slot == 1 ? s1 : slot == 2 ? s2 : s3;
    float v = s[(r & 1023) * CC + c];    // (b*256+t)*CC + c
    hilo(v, g_ah[idx], g_al[idx]);
}

// ---------------------------------------------------------------------------
// mma.sync GEMM: C = A * W^T (bf16 hi/lo x3), 128x128 tile, BK=32,
// 2-stage cp.async double buffer, 2 CTAs/SM.
// ---------------------------------------------------------------------------
#define MM_STAGE 40960
#define MM_TILE  10240

__global__ __launch_bounds__(256, 2) void k_mma(
    const __nv_bfloat16* __restrict__ Ah, const __nv_bfloat16* __restrict__ Al,
    const __nv_bfloat16* __restrict__ WhB, const __nv_bfloat16* __restrict__ WlB,
    float* __restrict__ C, int K, int ldc,
    int rpg, int wstride, int w0, int w1, int w2, int w3) {
    extern __shared__ __align__(128) uint8_t smraw[];
    const uint32_t smb = smem_u32(smraw);
    const int tid = threadIdx.x;
    const int wid = tid >> 5;
    const int lane = tid & 31;
    const int wm = wid >> 2;
    const int wn = wid & 3;
    const int row0 = blockIdx.y * 128;
    const int col0 = blockIdx.x * 128;
    const int wsel = wsel4(row0 / rpg, w0, w1, w2, w3);
    const __nv_bfloat16* Wh = WhB + (size_t)wsel * wstride;
    const __nv_bfloat16* Wl = WlB + (size_t)wsel * wstride;
    const int nc = K >> 5;

    float acc[4][4][4];
#pragma unroll
    for (int i = 0; i < 4; i++)
#pragma unroll
        for (int j = 0; j < 4; j++)
#pragma unroll
            for (int q = 0; q < 4; q++) acc[i][j][q] = 0.f;

    auto load_stage = [&](int kc, int st) {
        const int k0 = kc << 5;
        const uint32_t sb = smb + st * MM_STAGE;
#pragma unroll
        for (int p = 0; p < 8; p++) {
            int u = tid + (p << 8);
            int tile = u >> 9;
            int v = u & 511;
            int r = v >> 2, seg = v & 3;
            const __nv_bfloat16* src;
            if (tile == 0)      src = Ah + (size_t)(row0 + r) * K;
            else if (tile == 1) src = Al + (size_t)(row0 + r) * K;
            else if (tile == 2) src = Wh + (size_t)(col0 + r) * K;
            else                src = Wl + (size_t)(col0 + r) * K;
            CP16(sb + tile * MM_TILE + r * 80 + seg * 16, src + k0 + seg * 8);
        }
        CP_COMMIT();
    };

    load_stage(0, 0);
    CP_WAIT0();
    __syncthreads();

    const uint32_t aRowByte = (uint32_t)(wm * 64 + (lane & 15)) * 80 + ((lane >> 4) << 4);
    const uint32_t bRowByte = (uint32_t)(wn * 32 + (lane & 7)) * 80 + (((lane >> 3) & 1) << 4);

    for (int c = 0; c < nc; c++) {
        const int st = c & 1;
        if (c + 1 < nc) load_stage(c + 1, st ^ 1);
        const uint32_t sb = smb + st * MM_STAGE;
#pragma unroll
        for (int ks = 0; ks < 2; ks++) {
            uint32_t ah[4][4], al[4][4], bh[4][2], bl[4][2];
            const uint32_t kb = ks * 32;
#pragma unroll
            for (int mi = 0; mi < 4; mi++) {
                uint32_t ra = sb + aRowByte + (uint32_t)mi * 16 * 80 + kb;
                LDM4(ah[mi][0], ah[mi][1], ah[mi][2], ah[mi][3], ra);
                LDM4(al[mi][0], al[mi][1], al[mi][2], al[mi][3], ra + MM_TILE);
            }
#pragma unroll
            for (int ni = 0; ni < 4; ni++) {
                uint32_t rb = sb + 2 * MM_TILE + bRowByte + (uint32_t)ni * 8 * 80 + kb;
                LDM2(bh[ni][0], bh[ni][1], rb);
                LDM2(bl[ni][0], bl[ni][1], rb + MM_TILE);
            }
#pragma unroll
            for (int mi = 0; mi < 4; mi++)
#pragma unroll
                for (int ni = 0; ni < 4; ni++) {
                    MMA16816(acc[mi][ni], ah[mi], bh[ni]);
                    MMA16816(acc[mi][ni], ah[mi], bl[ni]);
                    MMA16816(acc[mi][ni], al[mi], bh[ni]);
                }
        }
        if (c + 1 < nc) CP_WAIT0();
        __syncthreads();
    }

    const int gr = lane >> 2;
    const int gc = (lane & 3) * 2;
#pragma unroll
    for (int mi = 0; mi < 4; mi++)
#pragma unroll
        for (int ni = 0; ni < 4; ni++) {
            int row = row0 + wm * 64 + mi * 16 + gr;
            int col = col0 + wn * 32 + ni * 8 + gc;
            float* p0 = C + (size_t)row * ldc + col;
            float* p1 = C + (size_t)(row + 8) * ldc + col;
            *(float2*)p0 = make_float2(acc[mi][ni][0], acc[mi][ni][1]);
            *(float2*)p1 = make_float2(acc[mi][ni][2], acc[mi][ni][3]);
        }
}

// ---------------------------------------------------------------------------
// 64x64 FFMA2 GEMM body (x_proj split-K, dt-proj)
// ---------------------------------------------------------------------------
__device__ __forceinline__ void gemm64_accum(
    const float* A, const float* W, unsigned long long acc[4][2],
    int K, int lda, int ldb, int row0, int col0) {
    __shared__ float As[16][68];
    __shared__ float Bs[16][68];
    const int tid = threadIdx.x;
    const int tx = tid & 15, ty = tid >> 4;
    for (int k0 = 0; k0 < K; k0 += 16) {
        __syncthreads();
#pragma unroll
        for (int i = 0; i < 4; i++) {
            int idx = tid + i * 256;
            int kk = idx & 15, rr = idx >> 4;
            As[kk][rr] = A[(size_t)(row0 + rr) * lda + k0 + kk];
            Bs[kk][rr] = W[(size_t)(col0 + rr) * ldb + k0 + kk];
        }
        __syncthreads();
#pragma unroll
        for (int kk = 0; kk < 16; kk++) {
            float a[4];
            *(float4*)a = *(const float4*)&As[kk][ty * 4];
            unsigned long long b2[2];
            *(float4*)b2 = *(const float4*)&Bs[kk][tx * 4];
#pragma unroll
            for (int i = 0; i < 4; i++) {
                unsigned long long ad;
                DUP2(ad, a[i]);
                FMA2(acc[i][0], ad, b2[0]);
                FMA2(acc[i][1], ad, b2[1]);
            }
        }
    }
}

__global__ __launch_bounds__(256) void k_gemm64sk(
    const float* __restrict__ A, const float* __restrict__ Wb,
    int rpg, int wstride, int w0, int w1, int w2, int w3) {
    const int row0 = blockIdx.y * 64;
    const int z = blockIdx.z;
    const int wsel = wsel4(row0 / rpg, w0, w1, w2, w3);
    const float* W = Wb + (size_t)wsel * wstride + z * 256;
    unsigned long long acc[4][2];
#pragma unroll
    for (int i = 0; i < 4; i++) { acc[i][0] = 0ull; acc[i][1] = 0ull; }
    gemm64_accum(A + z * 256, W, acc, 256, 1024, 1024, row0, 0);
    float* Cout = g_xdblp + (size_t)z * RTOK * 64;
    const int tx = threadIdx.x & 15, ty = threadIdx.x >> 4;
#pragma unroll
    for (int i = 0; i < 4; i++) {
        float* cp = Cout + (size_t)(row0 + ty * 4 + i) * 64 + tx * 4;
        *(ulonglong2*)cp = make_ulonglong2(acc[i][0], acc[i][1]);
    }
}

__global__ void k_reduce4() {
    int idx = blockIdx.x * blockDim.x + threadIdx.x;
    if (idx >= RTOK * 64) return;
    const int S = RTOK * 64;
    g_xdbl[idx] = (g_xdblp[idx] + g_xdblp[idx + S]) +
                  (g_xdblp[idx + 2 * S] + g_xdblp[idx + 3 * S]);
}

// dt-proj with fused +dtb and softplus -> g_delta
__global__ __launch_bounds__(256) void k_gemm64dt(
    const float* __restrict__ dtw, const float* __restrict__ dtb,
    int rpg, int w0, int w1, int w2, int w3) {
    const int row0 = blockIdx.y * 64;
    const int col0 = blockIdx.x * 64;
    const int m = wsel4(row0 / rpg, w0, w1, w2, w3);
    const float* W = dtw + (size_t)m * DIN * 32;
    unsigned long long acc[4][2];
#pragma unroll
    for (int i = 0; i < 4; i++) { acc[i][0] = 0ull; acc[i][1] = 0ull; }
    gemm64_accum(g_xdbl, W, acc, 32, 64, 32, row0, col0);
    const int tx = threadIdx.x & 15, ty = threadIdx.x >> 4;
#pragma unroll
    for (int i = 0; i < 4; i++) {
        const float* av = (const float*)acc[i];
        float r[4];
#pragma unroll
        for (int j = 0; j < 4; j++) {
            int col = col0 + tx * 4 + j;
            float x = av[j] + dtb[m * DIN + col];
            r[j] = (x > 15.f) ? x : __logf(1.f + __expf(x));
        }
        float* cp = g_delta + (size_t)(row0 + ty * 4 + i) * DIN + col0 + tx * 4;
        *(float4*)cp = make_float4(r[0], r[1], r[2], r[3]);
    }
}

// ---------------------------------------------------------------------------
// causal depthwise conv (4 taps) + bias + SiLU. dup=1: layer-0 compact-xz map.
// ---------------------------------------------------------------------------
__global__ void k_conv(const float* __restrict__ cw, const float* __restrict__ cb,
                       int T, int rpg, int w0, int w1, int w2, int w3, int dup) {
    int idx = blockIdx.x * blockDim.x + threadIdx.x;
    if (idx >= RTOK * DIN) return;
    int d = idx & (DIN - 1);
    int r = idx >> 10;
    int t = r & (T - 1);
    int m = wsel4(r / rpg, w0, w1, w2, w3);
    const float* cwp = cw + ((size_t)m * DIN + d) * 4;
    float acc = cb[m * DIN + d];
#pragma unroll
    for (int k = 0; k < 4; k++) {
        int tt = t - 3 + k;
        if (tt >= 0) {
            int row = xzrow(r + tt - t, dup);
            acc = fmaf(cwp[k], g_xz[(size_t)row * (2 * DIN) + d], acc);
        }
    }
    float e = __expf(-acc);
    g_x[idx] = __fdividef(acc, 1.f + e);
}

// ---------------------------------------------------------------------------
// Chunked selective scan (passes A, B, C).
// ---------------------------------------------------------------------------
template <bool CHAIN>
__device__ __forceinline__ void scanA_body(int rbase, int d, int g,
                                           const float Av[16], float Dv) {
    float h[16];
#pragma unroll
    for (int s = 0; s < 16; s++) h[s] = 0.f;
    float dsum = 0.f;
#pragma unroll 2
    for (int t = 0; t < 64; t++) {
        int r = rbase + t;
        float delta = g_delta[(size_t)r * DIN + d];
        float xv = g_x[(size_t)r * DIN + d];
        const float4* bc = (const float4*)(g_xdbl + (size_t)r * 64 + 32);
        float4 Bq[4], Cq[4];
#pragma unroll
        for (int q = 0; q < 4; q++) { Bq[q] = bc[q]; Cq[q] = bc[q + 4]; }
        const float* Bv = (const float*)Bq;
        const float* Cv = (const float*)Cq;
        dsum += delta;
        float p[16];
        if (CHAIN) powers16(__expf(delta * Av[0]), p);
        else {
#pragma unroll
            for (int s = 0; s < 16; s++) p[s] = __expf(delta * Av[s]);
        }
        float dx = delta * xv;
        float y0 = 0.f, y1 = 0.f, y2 = 0.f, y3 = 0.f;
#pragma unroll
        for (int s = 0; s < 16; s++) {
            h[s] = fmaf(h[s], p[s], dx * Bv[s]);
            float hv = h[s] * Cv[s];
            if ((s & 3) == 0) y0 += hv;
            else if ((s & 3) == 1) y1 += hv;
            else if ((s & 3) == 2) y2 += hv;
            else y3 += hv;
        }
        g_x[(size_t)r * DIN + d] = fmaf(Dv, xv, (y0 + y1) + (y2 + y3));
    }
    float P[16];
    if (CHAIN) powers16(__expf(dsum * Av[0]), P);
    else {
#pragma unroll
        for (int s = 0; s < 16; s++) P[s] = __expf(dsum * Av[s]);
    }
#pragma unroll
    for (int s = 0; s < 16; s++) {
        size_t o = ((size_t)(s * 128 + g) << 10) + d;
        g_hch[o] = h[s];
        g_xdblp[o] = P[s];   // P-chunk buffer (split-K partials are dead)
    }
}

__global__ __launch_bounds__(128) void k_scanA(const float* __restrict__ Alog,
                                               const float* __restrict__ Dp,
                                               int lgNCH, int w0, int w1, int w2, int w3) {
    int blk = blockIdx.x;
    int dg = blk & 7;
    int g = blk >> 3;
    int seq = g >> lgNCH;
    int d = (dg << 7) | threadIdx.x;
    int m = wsel4(seq >> 2, w0, w1, w2, w3);
    float Av[16];
    const float* ap = Alog + ((size_t)m * DIN + d) * 16;
#pragma unroll
    for (int s = 0; s < 16; s++) Av[s] = -__expf(ap[s]);
    bool chain = true;
#pragma unroll
    for (int s = 1; s < 16; s++)
        chain = chain &&
                (fabsf(Av[s] - (float)(s + 1) * Av[0]) <=
                 1e-3f * (float)(s + 1) * fabsf(Av[0]) + 1e-7f);
    float Dv = Dp[m * DIN + d];
    int rbase = g << 6;
    if (chain) scanA_body<true>(rbase, d, g, Av, Dv);
    else       scanA_body<false>(rbase, d, g, Av, Dv);
}

__global__ void k_scanB(int lgNCH, int nseq) {
    int idx = blockIdx.x * blockDim.x + threadIdx.x;
    if (idx >= nseq * DIN) return;
    int seq = idx >> 10;
    int d = idx & 1023;
    int NCH = 1 << lgNCH;
    float hin[16];
#pragma unroll
    for (int s = 0; s < 16; s++) hin[s] = 0.f;
    for (int j = 0; j < NCH; j++) {
        int g = (seq << lgNCH) + j;
#pragma unroll
        for (int s = 0; s < 16; s++) {
            size_t o = ((size_t)(s * 128 + g) << 10) + d;
            float hl = g_hch[o];
            float Pp = g_xdblp[o];
            g_hch[o] = hin[s];
            hin[s] = fmaf(Pp, hin[s], hl);
        }
    }
}

template <bool CHAIN>
__device__ __forceinline__ void scanC_body(int rbase, int d, int g, int dup,
                                           const float Av[16]) {
    float q[16];
#pragma unroll
    for (int s = 0; s < 16; s++)
        q[s] = g_hch[((size_t)(s * 128 + g) << 10) + d];
#pragma unroll 2
    for (int t = 0; t < 64; t++) {
        int r = rbase + t;
        float delta = g_delta[(size_t)r * DIN + d];
        float zv = g_xz[(size_t)xzrow(r, dup) * 2048 + 1024 + d];
        float ylin = g_x[(size_t)r * DIN + d];
        const float4* cp = (const float4*)(g_xdbl + (size_t)r * 64 + 48);
        float4 Cq[4];
#pragma unroll
        for (int u = 0; u < 4; u++) Cq[u] = cp[u];
        const float* Cv = (const float*)Cq;
        float p[16];
        if (CHAIN) powers16(__expf(delta * Av[0]), p);
        else {
#pragma unroll
            for (int s = 0; s < 16; s++) p[s] = __expf(delta * Av[s]);
        }
        float c0 = 0.f, c1 = 0.f, c2 = 0.f, c3 = 0.f;
#pragma unroll
        for (int s = 0; s < 16; s++) {
            q[s] *= p[s];
            float hv = q[s] * Cv[s];
            if ((s & 3) == 0) c0 += hv;
            else if ((s & 3) == 1) c1 += hv;
            else if ((s & 3) == 2) c2 += hv;
            else c3 += hv;
        }
        float y = ylin + (c0 + c1) + (c2 + c3);
        float sg = __fdividef(zv, 1.f + __expf(-zv));
        float yv = y * sg;
        hilo(yv, g_ah[(size_t)r * DIN + d], g_al[(size_t)r * DIN + d]);
    }
}

__global__ __launch_bounds__(128) void k_scanC(const float* __restrict__ Alog,
                                               int lgNCH, int w0, int w1, int w2, int w3,
                                               int dup) {
    int blk = blockIdx.x;
    int dg = blk & 7;
    int g = blk >> 3;
    int seq = g >> lgNCH;
    int j = g & ((1 << lgNCH) - 1);
    int d = (dg << 7) | threadIdx.x;
    int rbase = g << 6;
    if (j == 0) {
#pragma unroll 2
        for (int t = 0; t < 64; t++) {
            int r = rbase + t;
            float zv = g_xz[(size_t)xzrow(r, dup) * 2048 + 1024 + d];
            float ylin = g_x[(size_t)r * DIN + d];
            float sg = __fdividef(zv, 1.f + __expf(-zv));
            float yv = ylin * sg;
            hilo(yv, g_ah[(size_t)r * DIN + d], g_al[(size_t)r * DIN + d]);
        }
        return;
    }
    int m = wsel4(seq >> 2, w0, w1, w2, w3);
    float Av[16];
    const float* ap = Alog + ((size_t)m * DIN + d) * 16;
#pragma unroll
    for (int s = 0; s < 16; s++) Av[s] = -__expf(ap[s]);
    bool chain = true;
#pragma unroll
    for (int s = 1; s < 16; s++)
        chain = chain &&
                (fabsf(Av[s] - (float)(s + 1) * Av[0]) <=
                 1e-3f * (float)(s + 1) * fabsf(Av[0]) + 1e-7f);
    if (chain) scanC_body<true>(rbase, d, g, dup, Av);
    else       scanC_body<false>(rbase, d, g, dup, Av);
}

// ---------------------------------------------------------------------------
// layer-0 epilogue: fold halves, layernorm, residual; emit layer-1 GEMM input
// (forward + reversed copies) directly as bf16 hi/lo.
// ---------------------------------------------------------------------------
__global__ __launch_bounds__(128) void k_combine(
    const float* __restrict__ s0, const float* __restrict__ s1,
    const float* __restrict__ s2, const float* __restrict__ s3,
    const float* __restrict__ lnw, const float* __restrict__ lnb) {
    int blk = blockIdx.x;
    int t = blk & 255;
    int b = (blk >> 8) & 3;
    int slot = blk >> 10;
    const float* src = slot == 0 ? s0 : slot == 1 ? s1 : slot == 2 ? s2 : s3;
    int rowA = ((slot * 4 + b) * 512 + t) * CC;
    int rowB = ((slot * 4 + b) * 512 + (511 - t)) * CC;
    int tid = threadIdx.x;
    float v[4];
#pragma unroll
    for (int j = 0; j < 4; j++) {
        int c = tid + j * 128;
        v[j] = 0.5f * (g_o[rowA + c] + g_o[rowB + c]);
    }
    __shared__ float red[8];
    int wid = tid >> 5, lane = tid & 31;
    float s = (v[0] + v[1]) + (v[2] + v[3]);
#pragma unroll
    for (int o = 16; o; o >>= 1) s += __shfl_xor_sync(~0u, s, o);
    if (lane == 0) red[wid] = s;
    __syncthreads();
    float mean = (red[0] + red[1] + red[2] + red[3]) * (1.f / 512.f);
    float q = 0.f;
#pragma unroll
    for (int j = 0; j < 4; j++) { float dd = v[j] - mean; q = fmaf(dd, dd, q); }
#pragma unroll
    for (int o = 16; o; o >>= 1) q += __shfl_xor_sync(~0u, q, o);
    if (lane == 0) red[4 + wid] = q;
    __syncthreads();
    float var = (red[4] + red[5] + red[6] + red[7]) * (1.f / 512.f);
    float rstd = rsqrtf(var + 1e-5f);
    int tau = slot * 256 + t;
#pragma unroll
    for (int j = 0; j < 4; j++) {
        int c = tid + j * 128;
        float o = (v[j] - mean) * rstd * lnw[c] + lnb[c] + src[(b * 256 + t) * CC + c];
        __nv_bfloat16 hh, ll;
        hilo(o, hh, ll);
        int idxF = ((b * 1024) + tau) * CC + c;
        int idxR = (((4 + b) * 1024) + (1023 - tau)) * CC + c;
        g_ah[idxF] = hh; g_al[idxF] = ll;
        g_ah[idxR] = hh; g_al[idxR] = ll;
    }
}

__global__ void k_final(float* __restrict__ out) {
    int idx = blockIdx.x * blockDim.x + threadIdx.x;
    if (idx >= BB * 1024 * CC) return;
    int c = idx & (CC - 1);
    int rest = idx >> 9;
    int tau = rest & 1023;
    int b = rest >> 10;
    float f = 0.5f * (g_o[((b * 1024) + tau) * CC + c] +
                      g_o[(((4 + b) * 1024) + (1023 - tau)) * CC + c]);
    int i = tau >> 8;
    int t = tau & 255;
    out[(((i * 4 + b) * 256 + t) << 9) + c] = f;
}

// ---------------------------------------------------------------------------
extern "C" void kernel_launch(void* const* d_in, const int* in_sizes, int n_in,
                              void* d_out, int out_size) {
    const float* x0hw = (const float*)d_in[0];
    const float* x1hw = (const float*)d_in[1];
    const float* x0wh = (const float*)d_in[2];
    const float* x1wh = (const float*)d_in[3];
    const float* in_w = (const float*)d_in[4];
    const float* cw   = (const float*)d_in[5];
    const float* cb   = (const float*)d_in[6];
    const float* xw   = (const float*)d_in[7];
    const float* dtw  = (const float*)d_in[8];
    const float* dtb  = (const float*)d_in[9];
    const float* alog = (const float*)d_in[10];
    const float* Dp   = (const float*)d_in[11];
    const float* ow   = (const float*)d_in[12];
    const float* lnw  = (const float*)d_in[13];
    const float* lnb  = (const float*)d_in[14];
    float* out = (float*)d_out;

    float *pxz, *px, *po;
    cudaGetSymbolAddress((void**)&pxz, g_xz);
    cudaGetSymbolAddress((void**)&px, g_x);
    cudaGetSymbolAddress((void**)&po, g_o);
    __nv_bfloat16 *pah, *pal, *pwih, *pwil, *pwoh, *pwol;
    cudaGetSymbolAddress((void**)&pah, g_ah);
    cudaGetSymbolAddress((void**)&pal, g_al);
    cudaGetSymbolAddress((void**)&pwih, g_wih);
    cudaGetSymbolAddress((void**)&pwil, g_wil);
    cudaGetSymbolAddress((void**)&pwoh, g_woh);
    cudaGetSymbolAddress((void**)&pwol, g_wol);

    static int smem_set = 0;
    if (!smem_set) {
        cudaFuncSetAttribute(k_mma, cudaFuncAttributeMaxDynamicSharedMemorySize,
                             2 * MM_STAGE);
        smem_set = 1;
    }
    const int MMSMEM = 2 * MM_STAGE;

    const int EL = RTOK * DIN;
    const int ELF = BB * 1024 * CC;

    // weights -> bf16 hi/lo
    k_cvt<<<(6 * 2048 * 512 + 255) / 256, 256>>>(in_w, pwih, pwil, 6 * 2048 * 512);
    k_cvt<<<(6 * 512 * 1024 + 255) / 256, 256>>>(ow, pwoh, pwol, 6 * 512 * 1024);

    // ---------------- layer 0 (T=512, NCH=8, nseq=16; compact in_proj) ------
    {
        const int w0 = 0, w1 = 2, w2 = 1, w3 = 3, rpg = 2048, T = 512, lg = 3, nseq = 16;
        k_build4<<<(4096 * CC + 255) / 256, 256>>>(x0hw, x1hw, x0wh, x1wh);
        // in_proj on 4096 unique rows: rpg=1024 (slot groups of 1024 rows)
        k_mma<<<dim3(16, 32), 256, MMSMEM>>>(
            pah, pal, pwih, pwil, pxz, 512, 2048, 1024, 2048 * 512, w0, w1, w2, w3);
        k_conv<<<(EL + 255) / 256, 256>>>(cw, cb, T, rpg, w0, w1, w2, w3, 1);
        k_gemm64sk<<<dim3(1, RTOK / 64, 4), 256>>>(px, xw, rpg, 64 * 1024, w0, w1, w2, w3);
        k_reduce4<<<(RTOK * 64 + 255) / 256, 256>>>();
        k_gemm64dt<<<dim3(1024 / 64, RTOK / 64), 256>>>(dtw, dtb, rpg, w0, w1, w2, w3);
        k_scanA<<<1024, 128>>>(alog, Dp, lg, w0, w1, w2, w3);
        k_scanB<<<(nseq * DIN + 255) / 256, 256>>>(lg, nseq);
        k_scanC<<<1024, 128>>>(alog, lg, w0, w1, w2, w3, 1);
        k_mma<<<dim3(4, 64), 256, MMSMEM>>>(
            pah, pal, pwoh, pwol, po, 1024, 512, rpg, 512 * 1024, w0, w1, w2, w3);
        k_combine<<<4096, 128>>>(x0hw, x1hw, x0wh, x1wh, lnw, lnb);
    }

    // ---------------- layer 1 (T=1024, NCH=16, nseq=8) ----------------
    {
        const int w0 = 4, w1 = 5, w2 = 4, w3 = 5, rpg = 4096, T = 1024, lg = 4, nseq = 8;
        k_mma<<<dim3(16, 64), 256, MMSMEM>>>(
            pah, pal, pwih, pwil, pxz, 512, 2048, rpg, 2048 * 512, w0, w1, w2, w3);
        k_conv<<<(EL + 255) / 256, 256>>>(cw, cb, T, rpg, w0, w1, w2, w3, 0);
        k_gemm64sk<<<dim3(1, RTOK / 64, 4), 256>>>(px, xw, rpg, 64 * 1024, w0, w1, w2, w3);
        k_reduce4<<<(RTOK * 64 + 255) / 256, 256>>>();
        k_gemm64dt<<<dim3(1024 / 64, RTOK / 64), 256>>>(dtw, dtb, rpg, w0, w1, w2, w3);
        k_scanA<<<1024, 128>>>(alog, Dp, lg, w0, w1, w2, w3);
        k_scanB<<<(nseq * DIN + 255) / 256, 256>>>(lg, nseq);
        k_scanC<<<1024, 128>>>(alog, lg, w0, w1, w2, w3, 0);
        k_mma<<<dim3(4, 64), 256, MMSMEM>>>(
            pah, pal, pwoh, pwol, po, 1024, 512, rpg, 512 * 1024, w0, w1, w2, w3);
        k_final<<<(ELF + 255) / 256, 256>>>(out);
    }
}

// round 10
// speedup vs baseline: 1.0728x; 1.0062x over previous
#include <cuda_runtime.h>
#include <cuda_bf16.h>
#include <cstdint>

// ---------------------------------------------------------------------------
// MultiScaleMambaEncoder — mma.sync bf16 hi/lo x3 GEMMs + chunked parallel scan
// Layer-0 in_proj on 4096 unique rows; z-half of in_proj overlapped on a
// side stream (not needed until scanC).
// ---------------------------------------------------------------------------

#define BB 4
#define CC 512
#define DIN 1024
#define RTOK 8192

// fp32 scratch
__device__ float g_xz[RTOK * 2 * DIN];
__device__ float g_x[RTOK * DIN];          // conv output, then ylin (pass A)
__device__ float g_xdbl[RTOK * 64];
__device__ float g_xdblp[8 * RTOK * 64];   // split-K partials; head reused as P
__device__ float g_hch[16 * 128 * 1024];   // per-chunk local h, then h_in
__device__ float g_delta[RTOK * DIN];
__device__ float g_o[RTOK * CC];
// bf16 hi/lo scratch (GEMM A operands)
__device__ __nv_bfloat16 g_ah[RTOK * DIN];
__device__ __nv_bfloat16 g_al[RTOK * DIN];
__device__ __nv_bfloat16 g_wih[6 * 2048 * 512];
__device__ __nv_bfloat16 g_wil[6 * 2048 * 512];
__device__ __nv_bfloat16 g_woh[6 * 512 * 1024];
__device__ __nv_bfloat16 g_wol[6 * 512 * 1024];

__device__ __forceinline__ int wsel4(int ml, int w0, int w1, int w2, int w3) {
    return ml == 0 ? w0 : ml == 1 ? w1 : ml == 2 ? w2 : w3;
}

#define FMA2(d, a, b) asm("fma.rn.f32x2 %0, %1, %2, %0;" : "+l"(d) : "l"(a), "l"(b))
#define DUP2(d, s)    asm("mov.b64 %0, {%1, %1};" : "=l"(d) : "f"(s))

__device__ __forceinline__ uint32_t smem_u32(const void* p) {
    uint32_t a;
    asm("{ .reg .u64 t; cvta.to.shared.u64 t, %1; cvt.u32.u64 %0, t; }" : "=r"(a) : "l"(p));
    return a;
}
#define CP16(dst, src)  asm volatile("cp.async.cg.shared.global [%0], [%1], 16;" :: "r"(dst), "l"(src))
#define CP_COMMIT()     asm volatile("cp.async.commit_group;" ::: "memory")
#define CP_WAIT0()      asm volatile("cp.async.wait_group 0;" ::: "memory")

#define LDM4(r0, r1, r2, r3, a) \
    asm volatile("ldmatrix.sync.aligned.m8n8.x4.shared.b16 {%0,%1,%2,%3}, [%4];" \
                 : "=r"(r0), "=r"(r1), "=r"(r2), "=r"(r3) : "r"(a))
#define LDM2(r0, r1, a) \
    asm volatile("ldmatrix.sync.aligned.m8n8.x2.shared.b16 {%0,%1}, [%2];" \
                 : "=r"(r0), "=r"(r1) : "r"(a))
#define MMA16816(d, a, b) \
    asm volatile("mma.sync.aligned.m16n8k16.row.col.f32.bf16.bf16.f32 " \
                 "{%0,%1,%2,%3},{%4,%5,%6,%7},{%8,%9},{%0,%1,%2,%3};" \
                 : "+f"((d)[0]), "+f"((d)[1]), "+f"((d)[2]), "+f"((d)[3]) \
                 : "r"((a)[0]), "r"((a)[1]), "r"((a)[2]), "r"((a)[3]), \
                   "r"((b)[0]), "r"((b)[1]))

__device__ __forceinline__ void hilo(float v, __nv_bfloat16& h, __nv_bfloat16& l) {
    h = __float2bfloat16(v);
    l = __float2bfloat16(v - __bfloat162float(h));
}
// powers: p[s] = e1^(s+1), depth-4 ladder
__device__ __forceinline__ void powers16(float e1, float* p) {
    float e2 = e1 * e1, e4 = e2 * e2, e8 = e4 * e4;
    p[0] = e1;        p[1] = e2;        p[2] = e2 * e1;   p[3] = e4;
    p[4] = e4 * e1;   p[5] = e4 * e2;   p[6] = e4 * p[2]; p[7] = e8;
    p[8] = e8 * e1;   p[9] = e8 * e2;   p[10] = e8 * p[2]; p[11] = e8 * e4;
    p[12] = e8 * p[4]; p[13] = e8 * p[5]; p[14] = e8 * p[6]; p[15] = e8 * e8;
}
// layer-0 xz row map: r in [0,8192) -> unique row in [0,4096)
__device__ __forceinline__ int xzrow(int r, int dup) {
    if (!dup) return r;
    int t = r & 511;
    int tt = t < 256 ? t : 511 - t;
    return ((r >> 9) << 8) + tt;
}

// ---------------------------------------------------------------------------
__global__ void k_cvt(const float* __restrict__ src, __nv_bfloat16* __restrict__ hi,
                      __nv_bfloat16* __restrict__ lo, int n) {
    int i = blockIdx.x * blockDim.x + threadIdx.x;
    if (i >= n) return;
    float v = src[i];
    hilo(v, hi[i], lo[i]);
}

// layer-0 compact inputs: 4096 unique rows = (slot, b, t<256)
__global__ void k_build4(const float* __restrict__ s0, const float* __restrict__ s1,
                         const float* __restrict__ s2, const float* __restrict__ s3) {
    int idx = blockIdx.x * blockDim.x + threadIdx.x;
    if (idx >= 4096 * CC) return;
    int c = idx & (CC - 1);
    int r = idx >> 9;
    int slot = r >> 10;
    const float* s = slot == 0 ? s0 : slot == 1 ? s1 : slot == 2 ? s2 : s3;
    float v = s[(r & 1023) * CC + c];
    hilo(v, g_ah[idx], g_al[idx]);
}

// ---------------------------------------------------------------------------
// mma.sync GEMM: C = A * W^T (bf16 hi/lo x3), 128x128 tile, BK=32,
// 2-stage cp.async double buffer, 2 CTAs/SM.
// ---------------------------------------------------------------------------
#define MM_STAGE 40960
#define MM_TILE  10240

__global__ __launch_bounds__(256, 2) void k_mma(
    const __nv_bfloat16* __restrict__ Ah, const __nv_bfloat16* __restrict__ Al,
    const __nv_bfloat16* __restrict__ WhB, const __nv_bfloat16* __restrict__ WlB,
    float* __restrict__ C, int K, int ldc,
    int rpg, int wstride, int w0, int w1, int w2, int w3) {
    extern __shared__ __align__(128) uint8_t smraw[];
    const uint32_t smb = smem_u32(smraw);
    const int tid = threadIdx.x;
    const int wid = tid >> 5;
    const int lane = tid & 31;
    const int wm = wid >> 2;
    const int wn = wid & 3;
    const int row0 = blockIdx.y * 128;
    const int col0 = blockIdx.x * 128;
    const int wsel = wsel4(row0 / rpg, w0, w1, w2, w3);
    const __nv_bfloat16* Wh = WhB + (size_t)wsel * wstride;
    const __nv_bfloat16* Wl = WlB + (size_t)wsel * wstride;
    const int nc = K >> 5;

    float acc[4][4][4];
#pragma unroll
    for (int i = 0; i < 4; i++)
#pragma unroll
        for (int j = 0; j < 4; j++)
#pragma unroll
            for (int q = 0; q < 4; q++) acc[i][j][q] = 0.f;

    auto load_stage = [&](int kc, int st) {
        const int k0 = kc << 5;
        const uint32_t sb = smb + st * MM_STAGE;
#pragma unroll
        for (int p = 0; p < 8; p++) {
            int u = tid + (p << 8);
            int tile = u >> 9;
            int v = u & 511;
            int r = v >> 2, seg = v & 3;
            const __nv_bfloat16* src;
            if (tile == 0)      src = Ah + (size_t)(row0 + r) * K;
            else if (tile == 1) src = Al + (size_t)(row0 + r) * K;
            else if (tile == 2) src = Wh + (size_t)(col0 + r) * K;
            else                src = Wl + (size_t)(col0 + r) * K;
            CP16(sb + tile * MM_TILE + r * 80 + seg * 16, src + k0 + seg * 8);
        }
        CP_COMMIT();
    };

    load_stage(0, 0);
    CP_WAIT0();
    __syncthreads();

    const uint32_t aRowByte = (uint32_t)(wm * 64 + (lane & 15)) * 80 + ((lane >> 4) << 4);
    const uint32_t bRowByte = (uint32_t)(wn * 32 + (lane & 7)) * 80 + (((lane >> 3) & 1) << 4);

    for (int c = 0; c < nc; c++) {
        const int st = c & 1;
        if (c + 1 < nc) load_stage(c + 1, st ^ 1);
        const uint32_t sb = smb + st * MM_STAGE;
#pragma unroll
        for (int ks = 0; ks < 2; ks++) {
            uint32_t ah[4][4], al[4][4], bh[4][2], bl[4][2];
            const uint32_t kb = ks * 32;
#pragma unroll
            for (int mi = 0; mi < 4; mi++) {
                uint32_t ra = sb + aRowByte + (uint32_t)mi * 16 * 80 + kb;
                LDM4(ah[mi][0], ah[mi][1], ah[mi][2], ah[mi][3], ra);
                LDM4(al[mi][0], al[mi][1], al[mi][2], al[mi][3], ra + MM_TILE);
            }
#pragma unroll
            for (int ni = 0; ni < 4; ni++) {
                uint32_t rb = sb + 2 * MM_TILE + bRowByte + (uint32_t)ni * 8 * 80 + kb;
                LDM2(bh[ni][0], bh[ni][1], rb);
                LDM2(bl[ni][0], bl[ni][1], rb + MM_TILE);
            }
#pragma unroll
            for (int mi = 0; mi < 4; mi++)
#pragma unroll
                for (int ni = 0; ni < 4; ni++) {
                    MMA16816(acc[mi][ni], ah[mi], bh[ni]);
                    MMA16816(acc[mi][ni], ah[mi], bl[ni]);
                    MMA16816(acc[mi][ni], al[mi], bh[ni]);
                }
        }
        if (c + 1 < nc) CP_WAIT0();
        __syncthreads();
    }

    const int gr = lane >> 2;
    const int gc = (lane & 3) * 2;
#pragma unroll
    for (int mi = 0; mi < 4; mi++)
#pragma unroll
        for (int ni = 0; ni < 4; ni++) {
            int row = row0 + wm * 64 + mi * 16 + gr;
            int col = col0 + wn * 32 + ni * 8 + gc;
            float* p0 = C + (size_t)row * ldc + col;
            float* p1 = C + (size_t)(row + 8) * ldc + col;
            *(float2*)p0 = make_float2(acc[mi][ni][0], acc[mi][ni][1]);
            *(float2*)p1 = make_float2(acc[mi][ni][2], acc[mi][ni][3]);
        }
}

// ---------------------------------------------------------------------------
// 64x64 FFMA2 GEMM body (x_proj split-K, dt-proj)
// ---------------------------------------------------------------------------
__device__ __forceinline__ void gemm64_accum(
    const float* A, const float* W, unsigned long long acc[4][2],
    int K, int lda, int ldb, int row0, int col0) {
    __shared__ float As[16][68];
    __shared__ float Bs[16][68];
    const int tid = threadIdx.x;
    const int tx = tid & 15, ty = tid >> 4;
    for (int k0 = 0; k0 < K; k0 += 16) {
        __syncthreads();
#pragma unroll
        for (int i = 0; i < 4; i++) {
            int idx = tid + i * 256;
            int kk = idx & 15, rr = idx >> 4;
            As[kk][rr] = A[(size_t)(row0 + rr) * lda + k0 + kk];
            Bs[kk][rr] = W[(size_t)(col0 + rr) * ldb + k0 + kk];
        }
        __syncthreads();
#pragma unroll
        for (int kk = 0; kk < 16; kk++) {
            float a[4];
            *(float4*)a = *(const float4*)&As[kk][ty * 4];
            unsigned long long b2[2];
            *(float4*)b2 = *(const float4*)&Bs[kk][tx * 4];
#pragma unroll
            for (int i = 0; i < 4; i++) {
                unsigned long long ad;
                DUP2(ad, a[i]);
                FMA2(acc[i][0], ad, b2[0]);
                FMA2(acc[i][1], ad, b2[1]);
            }
        }
    }
}

// x_proj split-K (8 slices of K=128)
__global__ __launch_bounds__(256) void k_gemm64sk(
    const float* __restrict__ A, const float* __restrict__ Wb,
    int rpg, int wstride, int w0, int w1, int w2, int w3) {
    const int row0 = blockIdx.y * 64;
    const int z = blockIdx.z;
    const int wsel = wsel4(row0 / rpg, w0, w1, w2, w3);
    const float* W = Wb + (size_t)wsel * wstride + z * 128;
    unsigned long long acc[4][2];
#pragma unroll
    for (int i = 0; i < 4; i++) { acc[i][0] = 0ull; acc[i][1] = 0ull; }
    gemm64_accum(A + z * 128, W, acc, 128, 1024, 1024, row0, 0);
    float* Cout = g_xdblp + (size_t)z * RTOK * 64;
    const int tx = threadIdx.x & 15, ty = threadIdx.x >> 4;
#pragma unroll
    for (int i = 0; i < 4; i++) {
        float* cp = Cout + (size_t)(row0 + ty * 4 + i) * 64 + tx * 4;
        *(ulonglong2*)cp = make_ulonglong2(acc[i][0], acc[i][1]);
    }
}

__global__ void k_reduce8() {
    int idx = blockIdx.x * blockDim.x + threadIdx.x;
    if (idx >= RTOK * 64) return;
    const int S = RTOK * 64;
    float a0 = g_xdblp[idx] + g_xdblp[idx + S];
    float a1 = g_xdblp[idx + 2 * S] + g_xdblp[idx + 3 * S];
    float a2 = g_xdblp[idx + 4 * S] + g_xdblp[idx + 5 * S];
    float a3 = g_xdblp[idx + 6 * S] + g_xdblp[idx + 7 * S];
    g_xdbl[idx] = (a0 + a1) + (a2 + a3);
}

// dt-proj with fused +dtb and softplus -> g_delta
__global__ __launch_bounds__(256) void k_gemm64dt(
    const float* __restrict__ dtw, const float* __restrict__ dtb,
    int rpg, int w0, int w1, int w2, int w3) {
    const int row0 = blockIdx.y * 64;
    const int col0 = blockIdx.x * 64;
    const int m = wsel4(row0 / rpg, w0, w1, w2, w3);
    const float* W = dtw + (size_t)m * DIN * 32;
    unsigned long long acc[4][2];
#pragma unroll
    for (int i = 0; i < 4; i++) { acc[i][0] = 0ull; acc[i][1] = 0ull; }
    gemm64_accum(g_xdbl, W, acc, 32, 64, 32, row0, col0);
    const int tx = threadIdx.x & 15, ty = threadIdx.x >> 4;
#pragma unroll
    for (int i = 0; i < 4; i++) {
        const float* av = (const float*)acc[i];
        float r[4];
#pragma unroll
        for (int j = 0; j < 4; j++) {
            int col = col0 + tx * 4 + j;
            float x = av[j] + dtb[m * DIN + col];
            r[j] = (x > 15.f) ? x : __logf(1.f + __expf(x));
        }
        float* cp = g_delta + (size_t)(row0 + ty * 4 + i) * DIN + col0 + tx * 4;
        *(float4*)cp = make_float4(r[0], r[1], r[2], r[3]);
    }
}

// ---------------------------------------------------------------------------
// causal depthwise conv (4 taps) + bias + SiLU. dup=1: layer-0 compact-xz map.
// ---------------------------------------------------------------------------
__global__ void k_conv(const float* __restrict__ cw, const float* __restrict__ cb,
                       int T, int rpg, int w0, int w1, int w2, int w3, int dup) {
    int idx = blockIdx.x * blockDim.x + threadIdx.x;
    if (idx >= RTOK * DIN) return;
    int d = idx & (DIN - 1);
    int r = idx >> 10;
    int t = r & (T - 1);
    int m = wsel4(r / rpg, w0, w1, w2, w3);
    const float* cwp = cw + ((size_t)m * DIN + d) * 4;
    float acc = cb[m * DIN + d];
#pragma unroll
    for (int k = 0; k < 4; k++) {
        int tt = t - 3 + k;
        if (tt >= 0) {
            int row = xzrow(r + tt - t, dup);
            acc = fmaf(cwp[k], g_xz[(size_t)row * (2 * DIN) + d], acc);
        }
    }
    float e = __expf(-acc);
    g_x[idx] = __fdividef(acc, 1.f + e);
}

// ---------------------------------------------------------------------------
// Chunked selective scan (passes A, B, C).
// ---------------------------------------------------------------------------
template <bool CHAIN>
__device__ __forceinline__ void scanA_body(int rbase, int d, int g,
                                           const float Av[16], float Dv) {
    float h[16];
#pragma unroll
    for (int s = 0; s < 16; s++) h[s] = 0.f;
    float dsum = 0.f;
#pragma unroll 2
    for (int t = 0; t < 64; t++) {
        int r = rbase + t;
        float delta = g_delta[(size_t)r * DIN + d];
        float xv = g_x[(size_t)r * DIN + d];
        const float4* bc = (const float4*)(g_xdbl + (size_t)r * 64 + 32);
        float4 Bq[4], Cq[4];
#pragma unroll
        for (int q = 0; q < 4; q++) { Bq[q] = bc[q]; Cq[q] = bc[q + 4]; }
        const float* Bv = (const float*)Bq;
        const float* Cv = (const float*)Cq;
        dsum += delta;
        float p[16];
        if (CHAIN) powers16(__expf(delta * Av[0]), p);
        else {
#pragma unroll
            for (int s = 0; s < 16; s++) p[s] = __expf(delta * Av[s]);
        }
        float dx = delta * xv;
        float y0 = 0.f, y1 = 0.f, y2 = 0.f, y3 = 0.f;
#pragma unroll
        for (int s = 0; s < 16; s++) {
            h[s] = fmaf(h[s], p[s], dx * Bv[s]);
            float hv = h[s] * Cv[s];
            if ((s & 3) == 0) y0 += hv;
            else if ((s & 3) == 1) y1 += hv;
            else if ((s & 3) == 2) y2 += hv;
            else y3 += hv;
        }
        g_x[(size_t)r * DIN + d] = fmaf(Dv, xv, (y0 + y1) + (y2 + y3));
    }
    float P[16];
    if (CHAIN) powers16(__expf(dsum * Av[0]), P);
    else {
#pragma unroll
        for (int s = 0; s < 16; s++) P[s] = __expf(dsum * Av[s]);
    }
#pragma unroll
    for (int s = 0; s < 16; s++) {
        size_t o = ((size_t)(s * 128 + g) << 10) + d;
        g_hch[o] = h[s];
        g_xdblp[o] = P[s];   // P-chunk buffer (split-K partials are dead)
    }
}

__global__ __launch_bounds__(128) void k_scanA(const float* __restrict__ Alog,
                                               const float* __restrict__ Dp,
                                               int lgNCH, int w0, int w1, int w2, int w3) {
    int blk = blockIdx.x;
    int dg = blk & 7;
    int g = blk >> 3;
    int seq = g >> lgNCH;
    int d = (dg << 7) | threadIdx.x;
    int m = wsel4(seq >> 2, w0, w1, w2, w3);
    float Av[16];
    const float* ap = Alog + ((size_t)m * DIN + d) * 16;
#pragma unroll
    for (int s = 0; s < 16; s++) Av[s] = -__expf(ap[s]);
    bool chain = true;
#pragma unroll
    for (int s = 1; s < 16; s++)
        chain = chain &&
                (fabsf(Av[s] - (float)(s + 1) * Av[0]) <=
                 1e-3f * (float)(s + 1) * fabsf(Av[0]) + 1e-7f);
    float Dv = Dp[m * DIN + d];
    int rbase = g << 6;
    if (chain) scanA_body<true>(rbase, d, g, Av, Dv);
    else       scanA_body<false>(rbase, d, g, Av, Dv);
}

__global__ void k_scanB(int lgNCH, int nseq) {
    int idx = blockIdx.x * blockDim.x + threadIdx.x;
    if (idx >= nseq * DIN) return;
    int seq = idx >> 10;
    int d = idx & 1023;
    int NCH = 1 << lgNCH;
    float hin[16];
#pragma unroll
    for (int s = 0; s < 16; s++) hin[s] = 0.f;
    for (int j = 0; j < NCH; j++) {
        int g = (seq << lgNCH) + j;
#pragma unroll
        for (int s = 0; s < 16; s++) {
            size_t o = ((size_t)(s * 128 + g) << 10) + d;
            float hl = g_hch[o];
            float Pp = g_xdblp[o];
            g_hch[o] = hin[s];
            hin[s] = fmaf(Pp, hin[s], hl);
        }
    }
}

template <bool CHAIN>
__device__ __forceinline__ void scanC_body(int rbase, int d, int g, int dup,
                                           const float Av[16]) {
    float q[16];
#pragma unroll
    for (int s = 0; s < 16; s++)
        q[s] = g_hch[((size_t)(s * 128 + g) << 10) + d];
#pragma unroll 2
    for (int t = 0; t < 64; t++) {
        int r = rbase + t;
        float delta = g_delta[(size_t)r * DIN + d];
        float zv = g_xz[(size_t)xzrow(r, dup) * 2048 + 1024 + d];
        float ylin = g_x[(size_t)r * DIN + d];
        const float4* cp = (const float4*)(g_xdbl + (size_t)r * 64 + 48);
        float4 Cq[4];
#pragma unroll
        for (int u = 0; u < 4; u++) Cq[u] = cp[u];
        const float* Cv = (const float*)Cq;
        float p[16];
        if (CHAIN) powers16(__expf(delta * Av[0]), p);
        else {
#pragma unroll
            for (int s = 0; s < 16; s++) p[s] = __expf(delta * Av[s]);
        }
        float c0 = 0.f, c1 = 0.f, c2 = 0.f, c3 = 0.f;
#pragma unroll
        for (int s = 0; s < 16; s++) {
            q[s] *= p[s];
            float hv = q[s] * Cv[s];
            if ((s & 3) == 0) c0 += hv;
            else if ((s & 3) == 1) c1 += hv;
            else if ((s & 3) == 2) c2 += hv;
            else c3 += hv;
        }
        float y = ylin + (c0 + c1) + (c2 + c3);
        float sg = __fdividef(zv, 1.f + __expf(-zv));
        float yv = y * sg;
        hilo(yv, g_ah[(size_t)r * DIN + d], g_al[(size_t)r * DIN + d]);
    }
}

__global__ __launch_bounds__(128) void k_scanC(const float* __restrict__ Alog,
                                               int lgNCH, int w0, int w1, int w2, int w3,
                                               int dup) {
    int blk = blockIdx.x;
    int dg = blk & 7;
    int g = blk >> 3;
    int seq = g >> lgNCH;
    int j = g & ((1 << lgNCH) - 1);
    int d = (dg << 7) | threadIdx.x;
    int rbase = g << 6;
    if (j == 0) {
#pragma unroll 2
        for (int t = 0; t < 64; t++) {
            int r = rbase + t;
            float zv = g_xz[(size_t)xzrow(r, dup) * 2048 + 1024 + d];
            float ylin = g_x[(size_t)r * DIN + d];
            float sg = __fdividef(zv, 1.f + __expf(-zv));
            float yv = ylin * sg;
            hilo(yv, g_ah[(size_t)r * DIN + d], g_al[(size_t)r * DIN + d]);
        }
        return;
    }
    int m = wsel4(seq >> 2, w0, w1, w2, w3);
    float Av[16];
    const float* ap = Alog + ((size_t)m * DIN + d) * 16;
#pragma unroll
    for (int s = 0; s < 16; s++) Av[s] = -__expf(ap[s]);
    bool chain = true;
#pragma unroll
    for (int s = 1; s < 16; s++)
        chain = chain &&
                (fabsf(Av[s] - (float)(s + 1) * Av[0]) <=
                 1e-3f * (float)(s + 1) * fabsf(Av[0]) + 1e-7f);
    if (chain) scanC_body<true>(rbase, d, g, dup, Av);
    else       scanC_body<false>(rbase, d, g, dup, Av);
}

// ---------------------------------------------------------------------------
// layer-0 epilogue: fold halves, layernorm, residual; emit layer-1 GEMM input
// (forward + reversed copies) directly as bf16 hi/lo.
// ---------------------------------------------------------------------------
__global__ __launch_bounds__(128) void k_combine(
    const float* __restrict__ s0, const float* __restrict__ s1,
    const float* __restrict__ s2, const float* __restrict__ s3,
    const float* __restrict__ lnw, const float* __restrict__ lnb) {
    int blk = blockIdx.x;
    int t = blk & 255;
    int b = (blk >> 8) & 3;
    int slot = blk >> 10;
    const float* src = slot == 0 ? s0 : slot == 1 ? s1 : slot == 2 ? s2 : s3;
    int rowA = ((slot * 4 + b) * 512 + t) * CC;
    int rowB = ((slot * 4 + b) * 512 + (511 - t)) * CC;
    int tid = threadIdx.x;
    float v[4];
#pragma unroll
    for (int j = 0; j < 4; j++) {
        int c = tid + j * 128;
        v[j] = 0.5f * (g_o[rowA + c] + g_o[rowB + c]);
    }
    __shared__ float red[8];
    int wid = tid >> 5, lane = tid & 31;
    float s = (v[0] + v[1]) + (v[2] + v[3]);
#pragma unroll
    for (int o = 16; o; o >>= 1) s += __shfl_xor_sync(~0u, s, o);
    if (lane == 0) red[wid] = s;
    __syncthreads();
    float mean = (red[0] + red[1] + red[2] + red[3]) * (1.f / 512.f);
    float q = 0.f;
#pragma unroll
    for (int j = 0; j < 4; j++) { float dd = v[j] - mean; q = fmaf(dd, dd, q); }
#pragma unroll
    for (int o = 16; o; o >>= 1) q += __shfl_xor_sync(~0u, q, o);
    if (lane == 0) red[4 + wid] = q;
    __syncthreads();
    float var = (red[4] + red[5] + red[6] + red[7]) * (1.f / 512.f);
    float rstd = rsqrtf(var + 1e-5f);
    int tau = slot * 256 + t;
#pragma unroll
    for (int j = 0; j < 4; j++) {
        int c = tid + j * 128;
        float o = (v[j] - mean) * rstd * lnw[c] + lnb[c] + src[(b * 256 + t) * CC + c];
        __nv_bfloat16 hh, ll;
        hilo(o, hh, ll);
        int idxF = ((b * 1024) + tau) * CC + c;
        int idxR = (((4 + b) * 1024) + (1023 - tau)) * CC + c;
        g_ah[idxF] = hh; g_al[idxF] = ll;
        g_ah[idxR] = hh; g_al[idxR] = ll;
    }
}

__global__ void k_final(float* __restrict__ out) {
    int idx = blockIdx.x * blockDim.x + threadIdx.x;
    if (idx >= BB * 1024 * CC) return;
    int c = idx & (CC - 1);
    int rest = idx >> 9;
    int tau = rest & 1023;
    int b = rest >> 10;
    float f = 0.5f * (g_o[((b * 1024) + tau) * CC + c] +
                      g_o[(((4 + b) * 1024) + (1023 - tau)) * CC + c]);
    int i = tau >> 8;
    int t = tau & 255;
    out[(((i * 4 + b) * 256 + t) << 9) + c] = f;
}

// ---------------------------------------------------------------------------
extern "C" void kernel_launch(void* const* d_in, const int* in_sizes, int n_in,
                              void* d_out, int out_size) {
    const float* x0hw = (const float*)d_in[0];
    const float* x1hw = (const float*)d_in[1];
    const float* x0wh = (const float*)d_in[2];
    const float* x1wh = (const float*)d_in[3];
    const float* in_w = (const float*)d_in[4];
    const float* cw   = (const float*)d_in[5];
    const float* cb   = (const float*)d_in[6];
    const float* xw   = (const float*)d_in[7];
    const float* dtw  = (const float*)d_in[8];
    const float* dtb  = (const float*)d_in[9];
    const float* alog = (const float*)d_in[10];
    const float* Dp   = (const float*)d_in[11];
    const float* ow   = (const float*)d_in[12];
    const float* lnw  = (const float*)d_in[13];
    const float* lnb  = (const float*)d_in[14];
    float* out = (float*)d_out;

    float *pxz, *px, *po;
    cudaGetSymbolAddress((void**)&pxz, g_xz);
    cudaGetSymbolAddress((void**)&px, g_x);
    cudaGetSymbolAddress((void**)&po, g_o);
    __nv_bfloat16 *pah, *pal, *pwih, *pwil, *pwoh, *pwol;
    cudaGetSymbolAddress((void**)&pah, g_ah);
    cudaGetSymbolAddress((void**)&pal, g_al);
    cudaGetSymbolAddress((void**)&pwih, g_wih);
    cudaGetSymbolAddress((void**)&pwil, g_wil);
    cudaGetSymbolAddress((void**)&pwoh, g_woh);
    cudaGetSymbolAddress((void**)&pwol, g_wol);

    static int inited = 0;
    static cudaStream_t s2;
    static cudaEvent_t evX0, evZ0, evX1, evZ1;
    if (!inited) {
        cudaFuncSetAttribute(k_mma, cudaFuncAttributeMaxDynamicSharedMemorySize,
                             2 * MM_STAGE);
        cudaStreamCreateWithFlags(&s2, cudaStreamNonBlocking);
        cudaEventCreateWithFlags(&evX0, cudaEventDisableTiming);
        cudaEventCreateWithFlags(&evZ0, cudaEventDisableTiming);
        cudaEventCreateWithFlags(&evX1, cudaEventDisableTiming);
        cudaEventCreateWithFlags(&evZ1, cudaEventDisableTiming);
        inited = 1;
    }
    const int MMSMEM = 2 * MM_STAGE;

    const int EL = RTOK * DIN;
    const int ELF = BB * 1024 * CC;
    const size_t ZW = (size_t)1024 * 512;   // z-half weight row offset

    // weights -> bf16 hi/lo
    k_cvt<<<(6 * 2048 * 512 + 255) / 256, 256>>>(in_w, pwih, pwil, 6 * 2048 * 512);
    k_cvt<<<(6 * 512 * 1024 + 255) / 256, 256>>>(ow, pwoh, pwol, 6 * 512 * 1024);

    // ---------------- layer 0 (T=512, NCH=8, nseq=16; compact in_proj) ------
    {
        const int w0 = 0, w1 = 2, w2 = 1, w3 = 3, rpg = 2048, T = 512, lg = 3, nseq = 16;
        k_build4<<<(4096 * CC + 255) / 256, 256>>>(x0hw, x1hw, x0wh, x1wh);
        // in_proj x-half (cols 0..1023) on 4096 unique rows
        k_mma<<<dim3(8, 32), 256, MMSMEM>>>(
            pah, pal, pwih, pwil, pxz, 512, 2048, 1024, 2048 * 512, w0, w1, w2, w3);
        // fork: z-half on side stream (needed only by scanC)
        cudaEventRecord(evX0, 0);
        cudaStreamWaitEvent(s2, evX0, 0);
        k_mma<<<dim3(8, 32), 256, MMSMEM, s2>>>(
            pah, pal, pwih + ZW, pwil + ZW, pxz + 1024, 512, 2048,
            1024, 2048 * 512, w0, w1, w2, w3);
        cudaEventRecord(evZ0, s2);
        // main chain (x-dependent only)
        k_conv<<<(EL + 255) / 256, 256>>>(cw, cb, T, rpg, w0, w1, w2, w3, 1);
        k_gemm64sk<<<dim3(1, RTOK / 64, 8), 256>>>(px, xw, rpg, 64 * 1024, w0, w1, w2, w3);
        k_reduce8<<<(RTOK * 64 + 255) / 256, 256>>>();
        k_gemm64dt<<<dim3(1024 / 64, RTOK / 64), 256>>>(dtw, dtb, rpg, w0, w1, w2, w3);
        k_scanA<<<1024, 128>>>(alog, Dp, lg, w0, w1, w2, w3);
        k_scanB<<<(nseq * DIN + 255) / 256, 256>>>(lg, nseq);
        cudaStreamWaitEvent(0, evZ0, 0);   // join: scanC needs z
        k_scanC<<<1024, 128>>>(alog, lg, w0, w1, w2, w3, 1);
        k_mma<<<dim3(4, 64), 256, MMSMEM>>>(
            pah, pal, pwoh, pwol, po, 1024, 512, rpg, 512 * 1024, w0, w1, w2, w3);
        k_combine<<<4096, 128>>>(x0hw, x1hw, x0wh, x1wh, lnw, lnb);
    }

    // ---------------- layer 1 (T=1024, NCH=16, nseq=8) ----------------
    {
        const int w0 = 4, w1 = 5, w2 = 4, w3 = 5, rpg = 4096, T = 1024, lg = 4, nseq = 8;
        k_mma<<<dim3(8, 64), 256, MMSMEM>>>(
            pah, pal, pwih, pwil, pxz, 512, 2048, rpg, 2048 * 512, w0, w1, w2, w3);
        cudaEventRecord(evX1, 0);
        cudaStreamWaitEvent(s2, evX1, 0);
        k_mma<<<dim3(8, 64), 256, MMSMEM, s2>>>(
            pah, pal, pwih + ZW, pwil + ZW, pxz + 1024, 512, 2048,
            rpg, 2048 * 512, w0, w1, w2, w3);
        cudaEventRecord(evZ1, s2);
        k_conv<<<(EL + 255) / 256, 256>>>(cw, cb, T, rpg, w0, w1, w2, w3, 0);
        k_gemm64sk<<<dim3(1, RTOK / 64, 8), 256>>>(px, xw, rpg, 64 * 1024, w0, w1, w2, w3);
        k_reduce8<<<(RTOK * 64 + 255) / 256, 256>>>();
        k_gemm64dt<<<dim3(1024 / 64, RTOK / 64), 256>>>(dtw, dtb, rpg, w0, w1, w2, w3);
        k_scanA<<<1024, 128>>>(alog, Dp, lg, w0, w1, w2, w3);
        k_scanB<<<(nseq * DIN + 255) / 256, 256>>>(lg, nseq);
        cudaStreamWaitEvent(0, evZ1, 0);
        k_scanC<<<1024, 128>>>(alog, lg, w0, w1, w2, w3, 0);
        k_mma<<<dim3(4, 64), 256, MMSMEM>>>(
            pah, pal, pwoh, pwol, po, 1024, 512, rpg, 512 * 1024, w0, w1, w2, w3);
        k_final<<<(ELF + 255) / 256, 256>>>(out);
    }
}

// round 11
// speedup vs baseline: 1.2018x; 1.1202x over previous
#include <cuda_runtime.h>
#include <cuda_bf16.h>
#include <cstdint>

// ---------------------------------------------------------------------------
// MultiScaleMambaEncoder — mma.sync bf16 hi/lo x3 GEMMs + single-pass
// decoupled-lookback chunked scan. Layer-0 in_proj on 4096 unique rows;
// z-half of in_proj on a side stream.
// ---------------------------------------------------------------------------

#define BB 4
#define CC 512
#define DIN 1024
#define RTOK 8192

// fp32 scratch
__device__ float g_xz[RTOK * 2 * DIN];
__device__ float g_x[RTOK * DIN];          // conv output, then ylin
__device__ float g_xdbl[RTOK * 64];
__device__ float g_xdblp[8 * RTOK * 64];   // split-K partials
__device__ float g_hch[16 * 128 * 1024];   // published h_out per chunk
__device__ float g_delta[RTOK * DIN];
__device__ float g_o[RTOK * CC];
__device__ int   g_flag[1024];             // lookback flags
// bf16 hi/lo scratch (GEMM A operands)
__device__ __nv_bfloat16 g_ah[RTOK * DIN];
__device__ __nv_bfloat16 g_al[RTOK * DIN];
__device__ __nv_bfloat16 g_wih[6 * 2048 * 512];
__device__ __nv_bfloat16 g_wil[6 * 2048 * 512];
__device__ __nv_bfloat16 g_woh[6 * 512 * 1024];
__device__ __nv_bfloat16 g_wol[6 * 512 * 1024];

__device__ __forceinline__ int wsel4(int ml, int w0, int w1, int w2, int w3) {
    return ml == 0 ? w0 : ml == 1 ? w1 : ml == 2 ? w2 : w3;
}

#define FMA2(d, a, b) asm("fma.rn.f32x2 %0, %1, %2, %0;" : "+l"(d) : "l"(a), "l"(b))
#define DUP2(d, s)    asm("mov.b64 %0, {%1, %1};" : "=l"(d) : "f"(s))

__device__ __forceinline__ uint32_t smem_u32(const void* p) {
    uint32_t a;
    asm("{ .reg .u64 t; cvta.to.shared.u64 t, %1; cvt.u32.u64 %0, t; }" : "=r"(a) : "l"(p));
    return a;
}
#define CP16(dst, src)  asm volatile("cp.async.cg.shared.global [%0], [%1], 16;" :: "r"(dst), "l"(src))
#define CP_COMMIT()     asm volatile("cp.async.commit_group;" ::: "memory")
#define CP_WAIT0()      asm volatile("cp.async.wait_group 0;" ::: "memory")

#define LDM4(r0, r1, r2, r3, a) \
    asm volatile("ldmatrix.sync.aligned.m8n8.x4.shared.b16 {%0,%1,%2,%3}, [%4];" \
                 : "=r"(r0), "=r"(r1), "=r"(r2), "=r"(r3) : "r"(a))
#define LDM2(r0, r1, a) \
    asm volatile("ldmatrix.sync.aligned.m8n8.x2.shared.b16 {%0,%1}, [%2];" \
                 : "=r"(r0), "=r"(r1) : "r"(a))
#define MMA16816(d, a, b) \
    asm volatile("mma.sync.aligned.m16n8k16.row.col.f32.bf16.bf16.f32 " \
                 "{%0,%1,%2,%3},{%4,%5,%6,%7},{%8,%9},{%0,%1,%2,%3};" \
                 : "+f"((d)[0]), "+f"((d)[1]), "+f"((d)[2]), "+f"((d)[3]) \
                 : "r"((a)[0]), "r"((a)[1]), "r"((a)[2]), "r"((a)[3]), \
                   "r"((b)[0]), "r"((b)[1]))

__device__ __forceinline__ void hilo(float v, __nv_bfloat16& h, __nv_bfloat16& l) {
    h = __float2bfloat16(v);
    l = __float2bfloat16(v - __bfloat162float(h));
}
// powers: p[s] = e1^(s+1), depth-4 ladder
__device__ __forceinline__ void powers16(float e1, float* p) {
    float e2 = e1 * e1, e4 = e2 * e2, e8 = e4 * e4;
    p[0] = e1;        p[1] = e2;        p[2] = e2 * e1;   p[3] = e4;
    p[4] = e4 * e1;   p[5] = e4 * e2;   p[6] = e4 * p[2]; p[7] = e8;
    p[8] = e8 * e1;   p[9] = e8 * e2;   p[10] = e8 * p[2]; p[11] = e8 * e4;
    p[12] = e8 * p[4]; p[13] = e8 * p[5]; p[14] = e8 * p[6]; p[15] = e8 * e8;
}
// layer-0 xz row map: r in [0,8192) -> unique row in [0,4096)
__device__ __forceinline__ int xzrow(int r, int dup) {
    if (!dup) return r;
    int t = r & 511;
    int tt = t < 256 ? t : 511 - t;
    return ((r >> 9) << 8) + tt;
}

// ---------------------------------------------------------------------------
__global__ void k_cvt(const float* __restrict__ src, __nv_bfloat16* __restrict__ hi,
                      __nv_bfloat16* __restrict__ lo, int n) {
    int i = blockIdx.x * blockDim.x + threadIdx.x;
    if (i >= n) return;
    float v = src[i];
    hilo(v, hi[i], lo[i]);
}

// layer-0 compact inputs: 4096 unique rows = (slot, b, t<256)
__global__ void k_build4(const float* __restrict__ s0, const float* __restrict__ s1,
                         const float* __restrict__ s2, const float* __restrict__ s3) {
    int idx = blockIdx.x * blockDim.x + threadIdx.x;
    if (idx >= 4096 * CC) return;
    int c = idx & (CC - 1);
    int r = idx >> 9;
    int slot = r >> 10;
    const float* s = slot == 0 ? s0 : slot == 1 ? s1 : slot == 2 ? s2 : s3;
    float v = s[(r & 1023) * CC + c];
    hilo(v, g_ah[idx], g_al[idx]);
}

// ---------------------------------------------------------------------------
// mma.sync GEMM: C = A * W^T (bf16 hi/lo x3), 128x128 tile, BK=32,
// 2-stage cp.async double buffer, 2 CTAs/SM.
// ---------------------------------------------------------------------------
#define MM_STAGE 40960
#define MM_TILE  10240

__global__ __launch_bounds__(256, 2) void k_mma(
    const __nv_bfloat16* __restrict__ Ah, const __nv_bfloat16* __restrict__ Al,
    const __nv_bfloat16* __restrict__ WhB, const __nv_bfloat16* __restrict__ WlB,
    float* __restrict__ C, int K, int ldc,
    int rpg, int wstride, int w0, int w1, int w2, int w3) {
    extern __shared__ __align__(128) uint8_t smraw[];
    const uint32_t smb = smem_u32(smraw);
    const int tid = threadIdx.x;
    const int wid = tid >> 5;
    const int lane = tid & 31;
    const int wm = wid >> 2;
    const int wn = wid & 3;
    const int row0 = blockIdx.y * 128;
    const int col0 = blockIdx.x * 128;
    const int wsel = wsel4(row0 / rpg, w0, w1, w2, w3);
    const __nv_bfloat16* Wh = WhB + (size_t)wsel * wstride;
    const __nv_bfloat16* Wl = WlB + (size_t)wsel * wstride;
    const int nc = K >> 5;

    float acc[4][4][4];
#pragma unroll
    for (int i = 0; i < 4; i++)
#pragma unroll
        for (int j = 0; j < 4; j++)
#pragma unroll
            for (int q = 0; q < 4; q++) acc[i][j][q] = 0.f;

    auto load_stage = [&](int kc, int st) {
        const int k0 = kc << 5;
        const uint32_t sb = smb + st * MM_STAGE;
#pragma unroll
        for (int p = 0; p < 8; p++) {
            int u = tid + (p << 8);
            int tile = u >> 9;
            int v = u & 511;
            int r = v >> 2, seg = v & 3;
            const __nv_bfloat16* src;
            if (tile == 0)      src = Ah + (size_t)(row0 + r) * K;
            else if (tile == 1) src = Al + (size_t)(row0 + r) * K;
            else if (tile == 2) src = Wh + (size_t)(col0 + r) * K;
            else                src = Wl + (size_t)(col0 + r) * K;
            CP16(sb + tile * MM_TILE + r * 80 + seg * 16, src + k0 + seg * 8);
        }
        CP_COMMIT();
    };

    load_stage(0, 0);
    CP_WAIT0();
    __syncthreads();

    const uint32_t aRowByte = (uint32_t)(wm * 64 + (lane & 15)) * 80 + ((lane >> 4) << 4);
    const uint32_t bRowByte = (uint32_t)(wn * 32 + (lane & 7)) * 80 + (((lane >> 3) & 1) << 4);

    for (int c = 0; c < nc; c++) {
        const int st = c & 1;
        if (c + 1 < nc) load_stage(c + 1, st ^ 1);
        const uint32_t sb = smb + st * MM_STAGE;
#pragma unroll
        for (int ks = 0; ks < 2; ks++) {
            uint32_t ah[4][4], al[4][4], bh[4][2], bl[4][2];
            const uint32_t kb = ks * 32;
#pragma unroll
            for (int mi = 0; mi < 4; mi++) {
                uint32_t ra = sb + aRowByte + (uint32_t)mi * 16 * 80 + kb;
                LDM4(ah[mi][0], ah[mi][1], ah[mi][2], ah[mi][3], ra);
                LDM4(al[mi][0], al[mi][1], al[mi][2], al[mi][3], ra + MM_TILE);
            }
#pragma unroll
            for (int ni = 0; ni < 4; ni++) {
                uint32_t rb = sb + 2 * MM_TILE + bRowByte + (uint32_t)ni * 8 * 80 + kb;
                LDM2(bh[ni][0], bh[ni][1], rb);
                LDM2(bl[ni][0], bl[ni][1], rb + MM_TILE);
            }
#pragma unroll
            for (int mi = 0; mi < 4; mi++)
#pragma unroll
                for (int ni = 0; ni < 4; ni++) {
                    MMA16816(acc[mi][ni], ah[mi], bh[ni]);
                    MMA16816(acc[mi][ni], ah[mi], bl[ni]);
                    MMA16816(acc[mi][ni], al[mi], bh[ni]);
                }
        }
        if (c + 1 < nc) CP_WAIT0();
        __syncthreads();
    }

    const int gr = lane >> 2;
    const int gc = (lane & 3) * 2;
#pragma unroll
    for (int mi = 0; mi < 4; mi++)
#pragma unroll
        for (int ni = 0; ni < 4; ni++) {
            int row = row0 + wm * 64 + mi * 16 + gr;
            int col = col0 + wn * 32 + ni * 8 + gc;
            float* p0 = C + (size_t)row * ldc + col;
            float* p1 = C + (size_t)(row + 8) * ldc + col;
            *(float2*)p0 = make_float2(acc[mi][ni][0], acc[mi][ni][1]);
            *(float2*)p1 = make_float2(acc[mi][ni][2], acc[mi][ni][3]);
        }
}

// ---------------------------------------------------------------------------
// 64x64 FFMA2 GEMM body (x_proj split-K, dt-proj)
// ---------------------------------------------------------------------------
__device__ __forceinline__ void gemm64_accum(
    const float* A, const float* W, unsigned long long acc[4][2],
    int K, int lda, int ldb, int row0, int col0) {
    __shared__ float As[16][68];
    __shared__ float Bs[16][68];
    const int tid = threadIdx.x;
    const int tx = tid & 15, ty = tid >> 4;
    for (int k0 = 0; k0 < K; k0 += 16) {
        __syncthreads();
#pragma unroll
        for (int i = 0; i < 4; i++) {
            int idx = tid + i * 256;
            int kk = idx & 15, rr = idx >> 4;
            As[kk][rr] = A[(size_t)(row0 + rr) * lda + k0 + kk];
            Bs[kk][rr] = W[(size_t)(col0 + rr) * ldb + k0 + kk];
        }
        __syncthreads();
#pragma unroll
        for (int kk = 0; kk < 16; kk++) {
            float a[4];
            *(float4*)a = *(const float4*)&As[kk][ty * 4];
            unsigned long long b2[2];
            *(float4*)b2 = *(const float4*)&Bs[kk][tx * 4];
#pragma unroll
            for (int i = 0; i < 4; i++) {
                unsigned long long ad;
                DUP2(ad, a[i]);
                FMA2(acc[i][0], ad, b2[0]);
                FMA2(acc[i][1], ad, b2[1]);
            }
        }
    }
}

// x_proj split-K (8 slices of K=128)
__global__ __launch_bounds__(256) void k_gemm64sk(
    const float* __restrict__ A, const float* __restrict__ Wb,
    int rpg, int wstride, int w0, int w1, int w2, int w3) {
    const int row0 = blockIdx.y * 64;
    const int z = blockIdx.z;
    const int wsel = wsel4(row0 / rpg, w0, w1, w2, w3);
    const float* W = Wb + (size_t)wsel * wstride + z * 128;
    unsigned long long acc[4][2];
#pragma unroll
    for (int i = 0; i < 4; i++) { acc[i][0] = 0ull; acc[i][1] = 0ull; }
    gemm64_accum(A + z * 128, W, acc, 128, 1024, 1024, row0, 0);
    float* Cout = g_xdblp + (size_t)z * RTOK * 64;
    const int tx = threadIdx.x & 15, ty = threadIdx.x >> 4;
#pragma unroll
    for (int i = 0; i < 4; i++) {
        float* cp = Cout + (size_t)(row0 + ty * 4 + i) * 64 + tx * 4;
        *(ulonglong2*)cp = make_ulonglong2(acc[i][0], acc[i][1]);
    }
}

// reduce split-K partials; also zero lookback flags for the next scan
__global__ void k_reduce8() {
    int idx = blockIdx.x * blockDim.x + threadIdx.x;
    if (idx < 1024) g_flag[idx] = 0;
    if (idx >= RTOK * 64) return;
    const int S = RTOK * 64;
    float a0 = g_xdblp[idx] + g_xdblp[idx + S];
    float a1 = g_xdblp[idx + 2 * S] + g_xdblp[idx + 3 * S];
    float a2 = g_xdblp[idx + 4 * S] + g_xdblp[idx + 5 * S];
    float a3 = g_xdblp[idx + 6 * S] + g_xdblp[idx + 7 * S];
    g_xdbl[idx] = (a0 + a1) + (a2 + a3);
}

// dt-proj with fused +dtb and softplus -> g_delta
__global__ __launch_bounds__(256) void k_gemm64dt(
    const float* __restrict__ dtw, const float* __restrict__ dtb,
    int rpg, int w0, int w1, int w2, int w3) {
    const int row0 = blockIdx.y * 64;
    const int col0 = blockIdx.x * 64;
    const int m = wsel4(row0 / rpg, w0, w1, w2, w3);
    const float* W = dtw + (size_t)m * DIN * 32;
    unsigned long long acc[4][2];
#pragma unroll
    for (int i = 0; i < 4; i++) { acc[i][0] = 0ull; acc[i][1] = 0ull; }
    gemm64_accum(g_xdbl, W, acc, 32, 64, 32, row0, col0);
    const int tx = threadIdx.x & 15, ty = threadIdx.x >> 4;
#pragma unroll
    for (int i = 0; i < 4; i++) {
        const float* av = (const float*)acc[i];
        float r[4];
#pragma unroll
        for (int j = 0; j < 4; j++) {
            int col = col0 + tx * 4 + j;
            float x = av[j] + dtb[m * DIN + col];
            r[j] = (x > 15.f) ? x : __logf(1.f + __expf(x));
        }
        float* cp = g_delta + (size_t)(row0 + ty * 4 + i) * DIN + col0 + tx * 4;
        *(float4*)cp = make_float4(r[0], r[1], r[2], r[3]);
    }
}

// ---------------------------------------------------------------------------
// causal depthwise conv (4 taps) + bias + SiLU. dup=1: layer-0 compact-xz map.
// ---------------------------------------------------------------------------
__global__ void k_conv(const float* __restrict__ cw, const float* __restrict__ cb,
                       int T, int rpg, int w0, int w1, int w2, int w3, int dup) {
    int idx = blockIdx.x * blockDim.x + threadIdx.x;
    if (idx >= RTOK * DIN) return;
    int d = idx & (DIN - 1);
    int r = idx >> 10;
    int t = r & (T - 1);
    int m = wsel4(r / rpg, w0, w1, w2, w3);
    const float* cwp = cw + ((size_t)m * DIN + d) * 4;
    float acc = cb[m * DIN + d];
#pragma unroll
    for (int k = 0; k < 4; k++) {
        int tt = t - 3 + k;
        if (tt >= 0) {
            int row = xzrow(r + tt - t, dup);
            acc = fmaf(cwp[k], g_xz[(size_t)row * (2 * DIN) + d], acc);
        }
    }
    float e = __expf(-acc);
    g_x[idx] = __fdividef(acc, 1.f + e);
}

// ---------------------------------------------------------------------------
// Fused chunked scan with decoupled lookback (passes A+B+C in one kernel).
// Block (g, dg): local scan over 64 steps; publish h_out (flag release);
// spin for predecessor's h_out; correction + gate, writing bf16 hi/lo.
// Forward progress: block waits only on blk-8 (strictly lower bid).
// ---------------------------------------------------------------------------
template <bool CHAIN>
__device__ __forceinline__ void scanF_body(int rbase, int d, int g, int j,
                                           int blk, int dup,
                                           const float Av[16], float Dv) {
    const int tid = threadIdx.x;
    float h[16];
#pragma unroll
    for (int s = 0; s < 16; s++) h[s] = 0.f;
    float dsum = 0.f;
    // ---- local scan (h0 = 0); ylin (incl. D*x) overwrites g_x
#pragma unroll 2
    for (int t = 0; t < 64; t++) {
        int r = rbase + t;
        float delta = g_delta[(size_t)r * DIN + d];
        float xv = g_x[(size_t)r * DIN + d];
        const float4* bc = (const float4*)(g_xdbl + (size_t)r * 64 + 32);
        float4 Bq[4], Cq[4];
#pragma unroll
        for (int q = 0; q < 4; q++) { Bq[q] = bc[q]; Cq[q] = bc[q + 4]; }
        const float* Bv = (const float*)Bq;
        const float* Cv = (const float*)Cq;
        dsum += delta;
        float p[16];
        if (CHAIN) powers16(__expf(delta * Av[0]), p);
        else {
#pragma unroll
            for (int s = 0; s < 16; s++) p[s] = __expf(delta * Av[s]);
        }
        float dx = delta * xv;
        float y0 = 0.f, y1 = 0.f, y2 = 0.f, y3 = 0.f;
#pragma unroll
        for (int s = 0; s < 16; s++) {
            h[s] = fmaf(h[s], p[s], dx * Bv[s]);
            float hv = h[s] * Cv[s];
            if ((s & 3) == 0) y0 += hv;
            else if ((s & 3) == 1) y1 += hv;
            else if ((s & 3) == 2) y2 += hv;
            else y3 += hv;
        }
        g_x[(size_t)r * DIN + d] = fmaf(Dv, xv, (y0 + y1) + (y2 + y3));
    }

    float hin[16];
    if (j == 0) {
        // publish h_out = h_local; no wait
#pragma unroll
        for (int s = 0; s < 16; s++)
            g_hch[((size_t)(s * 128 + g) << 10) + d] = h[s];
        __threadfence();
        __syncthreads();
        if (tid == 0) atomicExch(&g_flag[blk], 1);
        // gate-only output
#pragma unroll 2
        for (int t = 0; t < 64; t++) {
            int r = rbase + t;
            float zv = g_xz[(size_t)xzrow(r, dup) * 2048 + 1024 + d];
            float ylin = g_x[(size_t)r * DIN + d];
            float sg = __fdividef(zv, 1.f + __expf(-zv));
            float yv = ylin * sg;
            hilo(yv, g_ah[(size_t)r * DIN + d], g_al[(size_t)r * DIN + d]);
        }
        return;
    }

    // chunk product P = prod dA over chunk
    float P[16];
    if (CHAIN) powers16(__expf(dsum * Av[0]), P);
    else {
#pragma unroll
        for (int s = 0; s < 16; s++) P[s] = __expf(dsum * Av[s]);
    }
    // ---- lookback: wait predecessor (blk - 8), read its h_out
    if (tid == 0) {
        while (atomicAdd(&g_flag[blk - 8], 0) == 0) __nanosleep(32);
    }
    __syncthreads();
    __threadfence();
#pragma unroll
    for (int s = 0; s < 16; s++)
        hin[s] = g_hch[((size_t)(s * 128 + (g - 1)) << 10) + d];
    // publish h_out = P*h_in + h_local ASAP to unblock successor
#pragma unroll
    for (int s = 0; s < 16; s++)
        g_hch[((size_t)(s * 128 + g) << 10) + d] = fmaf(P[s], hin[s], h[s]);
    __threadfence();
    __syncthreads();
    if (tid == 0) atomicExch(&g_flag[blk], 1);

    // ---- correction + gate (data L2-hot from local pass)
    float q[16];
#pragma unroll
    for (int s = 0; s < 16; s++) q[s] = hin[s];
#pragma unroll 2
    for (int t = 0; t < 64; t++) {
        int r = rbase + t;
        float delta = g_delta[(size_t)r * DIN + d];
        float zv = g_xz[(size_t)xzrow(r, dup) * 2048 + 1024 + d];
        float ylin = g_x[(size_t)r * DIN + d];
        const float4* cp = (const float4*)(g_xdbl + (size_t)r * 64 + 48);
        float4 Cq[4];
#pragma unroll
        for (int u = 0; u < 4; u++) Cq[u] = cp[u];
        const float* Cv = (const float*)Cq;
        float p[16];
        if (CHAIN) powers16(__expf(delta * Av[0]), p);
        else {
#pragma unroll
            for (int s = 0; s < 16; s++) p[s] = __expf(delta * Av[s]);
        }
        float c0 = 0.f, c1 = 0.f, c2 = 0.f, c3 = 0.f;
#pragma unroll
        for (int s = 0; s < 16; s++) {
            q[s] *= p[s];
            float hv = q[s] * Cv[s];
            if ((s & 3) == 0) c0 += hv;
            else if ((s & 3) == 1) c1 += hv;
            else if ((s & 3) == 2) c2 += hv;
            else c3 += hv;
        }
        float y = ylin + (c0 + c1) + (c2 + c3);
        float sg = __fdividef(zv, 1.f + __expf(-zv));
        float yv = y * sg;
        hilo(yv, g_ah[(size_t)r * DIN + d], g_al[(size_t)r * DIN + d]);
    }
}

__global__ __launch_bounds__(128) void k_scanF(const float* __restrict__ Alog,
                                               const float* __restrict__ Dp,
                                               int lgNCH, int w0, int w1, int w2, int w3,
                                               int dup) {
    int blk = blockIdx.x;
    int dg = blk & 7;
    int g = blk >> 3;
    int seq = g >> lgNCH;
    int j = g & ((1 << lgNCH) - 1);
    int d = (dg << 7) | threadIdx.x;
    int m = wsel4(seq >> 2, w0, w1, w2, w3);
    float Av[16];
    const float* ap = Alog + ((size_t)m * DIN + d) * 16;
#pragma unroll
    for (int s = 0; s < 16; s++) Av[s] = -__expf(ap[s]);
    bool chain = true;
#pragma unroll
    for (int s = 1; s < 16; s++)
        chain = chain &&
                (fabsf(Av[s] - (float)(s + 1) * Av[0]) <=
                 1e-3f * (float)(s + 1) * fabsf(Av[0]) + 1e-7f);
    float Dv = Dp[m * DIN + d];
    int rbase = g << 6;
    // chain flag is block-uniform (A depends only on m)
    if (chain) scanF_body<true>(rbase, d, g, j, blk, dup, Av, Dv);
    else       scanF_body<false>(rbase, d, g, j, blk, dup, Av, Dv);
}

// ---------------------------------------------------------------------------
// layer-0 epilogue: fold halves, layernorm, residual; emit layer-1 GEMM input
// (forward + reversed copies) directly as bf16 hi/lo.
// ---------------------------------------------------------------------------
__global__ __launch_bounds__(128) void k_combine(
    const float* __restrict__ s0, const float* __restrict__ s1,
    const float* __restrict__ s2, const float* __restrict__ s3,
    const float* __restrict__ lnw, const float* __restrict__ lnb) {
    int blk = blockIdx.x;
    int t = blk & 255;
    int b = (blk >> 8) & 3;
    int slot = blk >> 10;
    const float* src = slot == 0 ? s0 : slot == 1 ? s1 : slot == 2 ? s2 : s3;
    int rowA = ((slot * 4 + b) * 512 + t) * CC;
    int rowB = ((slot * 4 + b) * 512 + (511 - t)) * CC;
    int tid = threadIdx.x;
    float v[4];
#pragma unroll
    for (int j = 0; j < 4; j++) {
        int c = tid + j * 128;
        v[j] = 0.5f * (g_o[rowA + c] + g_o[rowB + c]);
    }
    __shared__ float red[8];
    int wid = tid >> 5, lane = tid & 31;
    float s = (v[0] + v[1]) + (v[2] + v[3]);
#pragma unroll
    for (int o = 16; o; o >>= 1) s += __shfl_xor_sync(~0u, s, o);
    if (lane == 0) red[wid] = s;
    __syncthreads();
    float mean = (red[0] + red[1] + red[2] + red[3]) * (1.f / 512.f);
    float q = 0.f;
#pragma unroll
    for (int j = 0; j < 4; j++) { float dd = v[j] - mean; q = fmaf(dd, dd, q); }
#pragma unroll
    for (int o = 16; o; o >>= 1) q += __shfl_xor_sync(~0u, q, o);
    if (lane == 0) red[4 + wid] = q;
    __syncthreads();
    float var = (red[4] + red[5] + red[6] + red[7]) * (1.f / 512.f);
    float rstd = rsqrtf(var + 1e-5f);
    int tau = slot * 256 + t;
#pragma unroll
    for (int j = 0; j < 4; j++) {
        int c = tid + j * 128;
        float o = (v[j] - mean) * rstd * lnw[c] + lnb[c] + src[(b * 256 + t) * CC + c];
        __nv_bfloat16 hh, ll;
        hilo(o, hh, ll);
        int idxF = ((b * 1024) + tau) * CC + c;
        int idxR = (((4 + b) * 1024) + (1023 - tau)) * CC + c;
        g_ah[idxF] = hh; g_al[idxF] = ll;
        g_ah[idxR] = hh; g_al[idxR] = ll;
    }
}

__global__ void k_final(float* __restrict__ out) {
    int idx = blockIdx.x * blockDim.x + threadIdx.x;
    if (idx >= BB * 1024 * CC) return;
    int c = idx & (CC - 1);
    int rest = idx >> 9;
    int tau = rest & 1023;
    int b = rest >> 10;
    float f = 0.5f * (g_o[((b * 1024) + tau) * CC + c] +
                      g_o[(((4 + b) * 1024) + (1023 - tau)) * CC + c]);
    int i = tau >> 8;
    int t = tau & 255;
    out[(((i * 4 + b) * 256 + t) << 9) + c] = f;
}

// ---------------------------------------------------------------------------
extern "C" void kernel_launch(void* const* d_in, const int* in_sizes, int n_in,
                              void* d_out, int out_size) {
    const float* x0hw = (const float*)d_in[0];
    const float* x1hw = (const float*)d_in[1];
    const float* x0wh = (const float*)d_in[2];
    const float* x1wh = (const float*)d_in[3];
    const float* in_w = (const float*)d_in[4];
    const float* cw   = (const float*)d_in[5];
    const float* cb   = (const float*)d_in[6];
    const float* xw   = (const float*)d_in[7];
    const float* dtw  = (const float*)d_in[8];
    const float* dtb  = (const float*)d_in[9];
    const float* alog = (const float*)d_in[10];
    const float* Dp   = (const float*)d_in[11];
    const float* ow   = (const float*)d_in[12];
    const float* lnw  = (const float*)d_in[13];
    const float* lnb  = (const float*)d_in[14];
    float* out = (float*)d_out;

    float *pxz, *px, *po;
    cudaGetSymbolAddress((void**)&pxz, g_xz);
    cudaGetSymbolAddress((void**)&px, g_x);
    cudaGetSymbolAddress((void**)&po, g_o);
    __nv_bfloat16 *pah, *pal, *pwih, *pwil, *pwoh, *pwol;
    cudaGetSymbolAddress((void**)&pah, g_ah);
    cudaGetSymbolAddress((void**)&pal, g_al);
    cudaGetSymbolAddress((void**)&pwih, g_wih);
    cudaGetSymbolAddress((void**)&pwil, g_wil);
    cudaGetSymbolAddress((void**)&pwoh, g_woh);
    cudaGetSymbolAddress((void**)&pwol, g_wol);

    static int inited = 0;
    static cudaStream_t s2;
    static cudaEvent_t evX0, evZ0, evX1, evZ1;
    if (!inited) {
        cudaFuncSetAttribute(k_mma, cudaFuncAttributeMaxDynamicSharedMemorySize,
                             2 * MM_STAGE);
        cudaStreamCreateWithFlags(&s2, cudaStreamNonBlocking);
        cudaEventCreateWithFlags(&evX0, cudaEventDisableTiming);
        cudaEventCreateWithFlags(&evZ0, cudaEventDisableTiming);
        cudaEventCreateWithFlags(&evX1, cudaEventDisableTiming);
        cudaEventCreateWithFlags(&evZ1, cudaEventDisableTiming);
        inited = 1;
    }
    const int MMSMEM = 2 * MM_STAGE;

    const int EL = RTOK * DIN;
    const int ELF = BB * 1024 * CC;
    const size_t ZW = (size_t)1024 * 512;

    // weights -> bf16 hi/lo
    k_cvt<<<(6 * 2048 * 512 + 255) / 256, 256>>>(in_w, pwih, pwil, 6 * 2048 * 512);
    k_cvt<<<(6 * 512 * 1024 + 255) / 256, 256>>>(ow, pwoh, pwol, 6 * 512 * 1024);

    // ---------------- layer 0 (T=512, NCH=8, nseq=16; compact in_proj) ------
    {
        const int w0 = 0, w1 = 2, w2 = 1, w3 = 3, rpg = 2048, T = 512, lg = 3;
        k_build4<<<(4096 * CC + 255) / 256, 256>>>(x0hw, x1hw, x0wh, x1wh);
        k_mma<<<dim3(8, 32), 256, MMSMEM>>>(
            pah, pal, pwih, pwil, pxz, 512, 2048, 1024, 2048 * 512, w0, w1, w2, w3);
        cudaEventRecord(evX0, 0);
        cudaStreamWaitEvent(s2, evX0, 0);
        k_mma<<<dim3(8, 32), 256, MMSMEM, s2>>>(
            pah, pal, pwih + ZW, pwil + ZW, pxz + 1024, 512, 2048,
            1024, 2048 * 512, w0, w1, w2, w3);
        cudaEventRecord(evZ0, s2);
        k_conv<<<(EL + 255) / 256, 256>>>(cw, cb, T, rpg, w0, w1, w2, w3, 1);
        k_gemm64sk<<<dim3(1, RTOK / 64, 8), 256>>>(px, xw, rpg, 64 * 1024, w0, w1, w2, w3);
        k_reduce8<<<(RTOK * 64 + 255) / 256, 256>>>();
        k_gemm64dt<<<dim3(1024 / 64, RTOK / 64), 256>>>(dtw, dtb, rpg, w0, w1, w2, w3);
        cudaStreamWaitEvent(0, evZ0, 0);   // scanF gates with z
        k_scanF<<<1024, 128>>>(alog, Dp, lg, w0, w1, w2, w3, 1);
        k_mma<<<dim3(4, 64), 256, MMSMEM>>>(
            pah, pal, pwoh, pwol, po, 1024, 512, rpg, 512 * 1024, w0, w1, w2, w3);
        k_combine<<<4096, 128>>>(x0hw, x1hw, x0wh, x1wh, lnw, lnb);
    }

    // ---------------- layer 1 (T=1024, NCH=16, nseq=8) ----------------
    {
        const int w0 = 4, w1 = 5, w2 = 4, w3 = 5, rpg = 4096, T = 1024, lg = 4;
        k_mma<<<dim3(8, 64), 256, MMSMEM>>>(
            pah, pal, pwih, pwil, pxz, 512, 2048, rpg, 2048 * 512, w0, w1, w2, w3);
        cudaEventRecord(evX1, 0);
        cudaStreamWaitEvent(s2, evX1, 0);
        k_mma<<<dim3(8, 64), 256, MMSMEM, s2>>>(
            pah, pal, pwih + ZW, pwil + ZW, pxz + 1024, 512, 2048,
            rpg, 2048 * 512, w0, w1, w2, w3);
        cudaEventRecord(evZ1, s2);
        k_conv<<<(EL + 255) / 256, 256>>>(cw, cb, T, rpg, w0, w1, w2, w3, 0);
        k_gemm64sk<<<dim3(1, RTOK / 64, 8), 256>>>(px, xw, rpg, 64 * 1024, w0, w1, w2, w3);
        k_reduce8<<<(RTOK * 64 + 255) / 256, 256>>>();
        k_gemm64dt<<<dim3(1024 / 64, RTOK / 64), 256>>>(dtw, dtb, rpg, w0, w1, w2, w3);
        cudaStreamWaitEvent(0, evZ1, 0);
        k_scanF<<<1024, 128>>>(alog, Dp, lg, w0, w1, w2, w3, 0);
        k_mma<<<dim3(4, 64), 256, MMSMEM>>>(
            pah, pal, pwoh, pwol, po, 1024, 512, rpg, 512 * 1024, w0, w1, w2, w3);
        k_final<<<(ELF + 255) / 256, 256>>>(out);
    }
}